// round 1
// baseline (speedup 1.0000x reference)
#include <cuda_runtime.h>
#include <cstdint>
#include <math.h>

#define BB   1024
#define SEQ  65
#define CC   1024
#define HH   16
#define DDIM 64
#define HID  4096
#define MTOT (BB*SEQ)   // 66560 = 520 * 128

// ---------------- scratch (device globals: no allocations allowed) ----------
__device__ float g_h  [(size_t)MTOT * CC];      // LN output (reused)
__device__ float g_qkv[(size_t)MTOT * 3 * CC];  // QKV GEMM output
__device__ float g_att[(size_t)MTOT * CC];      // attention output [B,N,C]
__device__ float g_act[(size_t)MTOT * HID];     // gelu(fc1) activations

// ---------------- helpers ---------------------------------------------------
__device__ __forceinline__ uint32_t f2tf32(float f) {
    uint32_t u;
    asm("cvt.rna.tf32.f32 %0, %1;" : "=r"(u) : "f"(f));
    return u;
}

__device__ __forceinline__ void mma_tf32(float c[4], const uint32_t a[4], const uint32_t b[2]) {
    asm volatile(
        "mma.sync.aligned.m16n8k8.row.col.f32.tf32.tf32.f32 "
        "{%0,%1,%2,%3}, {%4,%5,%6,%7}, {%8,%9}, {%0,%1,%2,%3};\n"
        : "+f"(c[0]), "+f"(c[1]), "+f"(c[2]), "+f"(c[3])
        : "r"(a[0]), "r"(a[1]), "r"(a[2]), "r"(a[3]), "r"(b[0]), "r"(b[1]));
}

__device__ __forceinline__ float gelu_tanh(float x) {
    float x3 = x * x * x;
    return 0.5f * x * (1.0f + tanhf(0.7978845608028654f * (x + 0.044715f * x3)));
}

// ---------------- LayerNorm: one block per row (C = 1024) -------------------
__global__ __launch_bounds__(256)
void ln_kernel(const float* __restrict__ x, const float* __restrict__ g,
               const float* __restrict__ b, float* __restrict__ y) {
    int row = blockIdx.x;
    const float4* xr = (const float4*)(x + (size_t)row * CC);
    float4 v = xr[threadIdx.x];
    float s1 = v.x + v.y + v.z + v.w;
    float s2 = v.x * v.x + v.y * v.y + v.z * v.z + v.w * v.w;
    #pragma unroll
    for (int o = 16; o; o >>= 1) {
        s1 += __shfl_xor_sync(0xffffffffu, s1, o);
        s2 += __shfl_xor_sync(0xffffffffu, s2, o);
    }
    __shared__ float r1[8], r2[8];
    int w = threadIdx.x >> 5;
    if ((threadIdx.x & 31) == 0) { r1[w] = s1; r2[w] = s2; }
    __syncthreads();
    s1 = 0.f; s2 = 0.f;
    #pragma unroll
    for (int i = 0; i < 8; i++) { s1 += r1[i]; s2 += r2[i]; }
    float mu  = s1 * (1.0f / CC);
    float var = s2 * (1.0f / CC) - mu * mu;
    float rs  = rsqrtf(var + 1e-5f);
    float4 gv = ((const float4*)g)[threadIdx.x];
    float4 bv = ((const float4*)b)[threadIdx.x];
    float4 o;
    o.x = (v.x - mu) * rs * gv.x + bv.x;
    o.y = (v.y - mu) * rs * gv.y + bv.y;
    o.z = (v.z - mu) * rs * gv.z + bv.z;
    o.w = (v.w - mu) * rs * gv.w + bv.w;
    ((float4*)(y + (size_t)row * CC))[threadIdx.x] = o;
}

// ---------------- TF32 tensor-core GEMM:  out = A[M,K] @ W[N,K]^T + epi -----
// Tiles: CTA 128x128x32, 8 warps (4 along M x 2 along N), warp 32x64,
// mma m16n8k8. Smem rows stride 40 words (40 % 32 == 8) => fragment LDS
// bank pattern 8*g + t : conflict-free.
enum { EPI_BIAS = 0, EPI_RES = 1, EPI_GELU = 2 };

template <int EPI>
__global__ __launch_bounds__(256, 2)
void gemm_tf32(const float* __restrict__ A, const float* __restrict__ W,
               const float* __restrict__ bias, const float* res,
               float* out, int K, int N) {
    __shared__ uint32_t As[128 * 40];
    __shared__ uint32_t Bs[128 * 40];

    int tid  = threadIdx.x;
    int bm   = blockIdx.y * 128;
    int bn   = blockIdx.x * 128;
    int r    = tid >> 3, kq = tid & 7;            // loaders: 32 rows x 8 k-quads
    int w    = tid >> 5, lane = tid & 31;
    int g    = lane >> 2, t = lane & 3;
    int wm   = (w & 3) * 32, wn = (w >> 2) * 64;

    float acc[2][8][4];
    #pragma unroll
    for (int mt = 0; mt < 2; mt++)
        #pragma unroll
        for (int nt = 0; nt < 8; nt++)
            #pragma unroll
            for (int q = 0; q < 4; q++) acc[mt][nt][q] = 0.f;

    const float* Abase = A + (size_t)bm * K;
    const float* Wbase = W + (size_t)bn * K;
    int nk = K >> 5;

    for (int kt = 0; kt < nk; kt++) {
        int k0 = kt * 32;
        __syncthreads();
        #pragma unroll
        for (int i = 0; i < 4; i++) {
            int row = r + 32 * i;
            float4 av = *(const float4*)(Abase + (size_t)row * K + k0 + kq * 4);
            uint32_t* da = &As[row * 40 + kq * 4];
            da[0] = f2tf32(av.x); da[1] = f2tf32(av.y);
            da[2] = f2tf32(av.z); da[3] = f2tf32(av.w);
            float4 bv = *(const float4*)(Wbase + (size_t)row * K + k0 + kq * 4);
            uint32_t* db = &Bs[row * 40 + kq * 4];
            db[0] = f2tf32(bv.x); db[1] = f2tf32(bv.y);
            db[2] = f2tf32(bv.z); db[3] = f2tf32(bv.w);
        }
        __syncthreads();

        #pragma unroll
        for (int kk = 0; kk < 32; kk += 8) {
            uint32_t af[2][4];
            #pragma unroll
            for (int mt = 0; mt < 2; mt++) {
                int r0 = wm + mt * 16 + g;
                af[mt][0] = As[r0 * 40 + kk + t];
                af[mt][1] = As[(r0 + 8) * 40 + kk + t];
                af[mt][2] = As[r0 * 40 + kk + t + 4];
                af[mt][3] = As[(r0 + 8) * 40 + kk + t + 4];
            }
            uint32_t bf[8][2];
            #pragma unroll
            for (int nt = 0; nt < 8; nt++) {
                int c0 = wn + nt * 8 + g;
                bf[nt][0] = Bs[c0 * 40 + kk + t];
                bf[nt][1] = Bs[c0 * 40 + kk + t + 4];
            }
            #pragma unroll
            for (int mt = 0; mt < 2; mt++)
                #pragma unroll
                for (int nt = 0; nt < 8; nt++)
                    mma_tf32(acc[mt][nt], af[mt], bf[nt]);
        }
    }

    // epilogue
    #pragma unroll
    for (int mt = 0; mt < 2; mt++) {
        #pragma unroll
        for (int nt = 0; nt < 8; nt++) {
            int rr0 = bm + wm + mt * 16 + g;
            int cc  = bn + wn + nt * 8 + 2 * t;
            float b0 = bias[cc], b1 = bias[cc + 1];
            #pragma unroll
            for (int hh = 0; hh < 2; hh++) {
                int rr  = rr0 + hh * 8;
                float v0 = acc[mt][nt][hh * 2 + 0] + b0;
                float v1 = acc[mt][nt][hh * 2 + 1] + b1;
                if (EPI == EPI_RES) {
                    v0 += res[(size_t)rr * N + cc];
                    v1 += res[(size_t)rr * N + cc + 1];
                }
                if (EPI == EPI_GELU) {
                    v0 = gelu_tanh(v0);
                    v1 = gelu_tanh(v1);
                }
                *(float2*)(out + (size_t)rr * N + cc) = make_float2(v0, v1);
            }
        }
    }
}

// ---------------- Attention: one block per (b,h), fp32 SIMT ----------------
// logits = Q K^T * 0.125 + bias_scale * bias[h]; softmax; O = P V
// 128 threads as 16(ty) x 8(tx); 45/40 accumulators per thread.
__global__ __launch_bounds__(128)
void attn_kernel(const float* __restrict__ qkv, const float* __restrict__ abias,
                 const float* __restrict__ bscale_p, float* __restrict__ out) {
    __shared__ float sq[65 * 65];   // Q, later reused for P
    __shared__ float skv[65 * 65];  // K, later reused for V

    int bh = blockIdx.x;
    int b  = bh >> 4, h = bh & 15;
    int tid = threadIdx.x;
    size_t base = (size_t)b * SEQ * 3072 + (size_t)h * 64;

    for (int idx = tid; idx < 65 * 64; idx += 128) {
        int n = idx >> 6, d = idx & 63;
        size_t gsrc = base + (size_t)n * 3072 + d;
        sq [n * 65 + d] = qkv[gsrc];          // Q
        skv[n * 65 + d] = qkv[gsrc + 1024];   // K
    }
    __syncthreads();

    float bsc = *bscale_p;
    int ty = tid >> 3, tx = tid & 7;

    float acc[5][9];
    #pragma unroll
    for (int i = 0; i < 5; i++)
        #pragma unroll
        for (int j = 0; j < 9; j++) acc[i][j] = 0.f;

    for (int d = 0; d < 64; d++) {
        float qv[5], kv[9];
        #pragma unroll
        for (int i = 0; i < 5; i++) {
            int n = ty + 16 * i; if (n > 64) n = 64;
            qv[i] = sq[n * 65 + d];
        }
        #pragma unroll
        for (int j = 0; j < 9; j++) {
            int m = tx + 8 * j; if (m > 64) m = 64;
            kv[j] = skv[m * 65 + d];
        }
        #pragma unroll
        for (int i = 0; i < 5; i++)
            #pragma unroll
            for (int j = 0; j < 9; j++)
                acc[i][j] += qv[i] * kv[j];
    }

    const float NEG = -1e30f;
    #pragma unroll
    for (int i = 0; i < 5; i++) {
        int n = ty + 16 * i;
        bool valid = (n <= 64);
        int nc = valid ? n : 64;
        const float* brow = abias + ((size_t)h * 65 + nc) * 65;

        float l[9];
        float mx = NEG;
        #pragma unroll
        for (int j = 0; j < 9; j++) {
            int m = tx + 8 * j;
            float lv = NEG;
            if (valid && m <= 64) lv = acc[i][j] * 0.125f + bsc * brow[m];
            l[j] = lv;
            mx = fmaxf(mx, lv);
        }
        mx = fmaxf(mx, __shfl_xor_sync(0xffffffffu, mx, 1));
        mx = fmaxf(mx, __shfl_xor_sync(0xffffffffu, mx, 2));
        mx = fmaxf(mx, __shfl_xor_sync(0xffffffffu, mx, 4));
        float s = 0.f;
        #pragma unroll
        for (int j = 0; j < 9; j++) { l[j] = __expf(l[j] - mx); s += l[j]; }
        s += __shfl_xor_sync(0xffffffffu, s, 1);
        s += __shfl_xor_sync(0xffffffffu, s, 2);
        s += __shfl_xor_sync(0xffffffffu, s, 4);
        float inv = 1.0f / s;
        #pragma unroll
        for (int j = 0; j < 9; j++) {
            int m = tx + 8 * j;
            if (valid && m <= 64) sq[n * 65 + m] = l[j] * inv;  // write P
        }
    }
    __syncthreads();

    for (int idx = tid; idx < 65 * 64; idx += 128) {   // V overwrites K
        int n = idx >> 6, d = idx & 63;
        skv[n * 65 + d] = qkv[base + (size_t)n * 3072 + d + 2048];
    }
    __syncthreads();

    float acc2[5][8];
    #pragma unroll
    for (int i = 0; i < 5; i++)
        #pragma unroll
        for (int j = 0; j < 8; j++) acc2[i][j] = 0.f;

    for (int m = 0; m <= 64; m++) {
        float pv[5], vv[8];
        #pragma unroll
        for (int i = 0; i < 5; i++) {
            int n = ty + 16 * i; if (n > 64) n = 64;
            pv[i] = sq[n * 65 + m];
        }
        #pragma unroll
        for (int j = 0; j < 8; j++)
            vv[j] = skv[m * 65 + tx + 8 * j];
        #pragma unroll
        for (int i = 0; i < 5; i++)
            #pragma unroll
            for (int j = 0; j < 8; j++)
                acc2[i][j] += pv[i] * vv[j];
    }

    size_t obase = (size_t)b * SEQ * 1024 + (size_t)h * 64;
    #pragma unroll
    for (int i = 0; i < 5; i++) {
        int n = ty + 16 * i;
        if (n <= 64) {
            #pragma unroll
            for (int j = 0; j < 8; j++)
                out[obase + (size_t)n * 1024 + tx + 8 * j] = acc2[i][j];
        }
    }
}

// ---------------- launch -----------------------------------------------------
extern "C" void kernel_launch(void* const* d_in, const int* in_sizes, int n_in,
                              void* d_out, int out_size) {
    const float* x        = (const float*)d_in[0];
    const float* ln1_g    = (const float*)d_in[1];
    const float* ln1_b    = (const float*)d_in[2];
    const float* qkv_w    = (const float*)d_in[3];
    const float* qkv_b    = (const float*)d_in[4];
    const float* proj_w   = (const float*)d_in[5];
    const float* proj_b   = (const float*)d_in[6];
    const float* attnbias = (const float*)d_in[7];
    const float* bscale   = (const float*)d_in[8];
    const float* ln2_g    = (const float*)d_in[9];
    const float* ln2_b    = (const float*)d_in[10];
    const float* fc1_w    = (const float*)d_in[11];
    const float* fc1_b    = (const float*)d_in[12];
    const float* fc2_w    = (const float*)d_in[13];
    const float* fc2_b    = (const float*)d_in[14];
    float* out = (float*)d_out;

    float *h, *qkv, *att, *act;
    cudaGetSymbolAddress((void**)&h,   g_h);
    cudaGetSymbolAddress((void**)&qkv, g_qkv);
    cudaGetSymbolAddress((void**)&att, g_att);
    cudaGetSymbolAddress((void**)&act, g_act);

    // 1. h = LN1(x)
    ln_kernel<<<MTOT, 256>>>(x, ln1_g, ln1_b, h);
    // 2. qkv = h @ qkv_w^T + qkv_b
    gemm_tf32<EPI_BIAS><<<dim3(3 * CC / 128, MTOT / 128), 256>>>(
        h, qkv_w, qkv_b, nullptr, qkv, CC, 3 * CC);
    // 3. attention -> att [B,N,C]
    attn_kernel<<<BB * HH, 128>>>(qkv, attnbias, bscale, att);
    // 4. out = x + att @ proj_w^T + proj_b
    gemm_tf32<EPI_RES><<<dim3(CC / 128, MTOT / 128), 256>>>(
        att, proj_w, proj_b, x, out, CC, CC);
    // 5. h = LN2(out)
    ln_kernel<<<MTOT, 256>>>(out, ln2_g, ln2_b, h);
    // 6. act = gelu(h @ fc1_w^T + fc1_b)
    gemm_tf32<EPI_GELU><<<dim3(HID / 128, MTOT / 128), 256>>>(
        h, fc1_w, fc1_b, nullptr, act, CC, HID);
    // 7. out = out + act @ fc2_w^T + fc2_b
    gemm_tf32<EPI_RES><<<dim3(CC / 128, MTOT / 128), 256>>>(
        act, fc2_w, fc2_b, out, out, HID, CC);
}

// round 3
// speedup vs baseline: 1.3527x; 1.3527x over previous
#include <cuda_runtime.h>
#include <cstdint>
#include <math.h>

#define BB   1024
#define SEQ  65
#define CC   1024
#define HH   16
#define HID  4096
#define MTOT (BB*SEQ)   // 66560 = 520 * 128

// ---------------- scratch (device globals: no allocations allowed) ----------
__device__ float g_h  [(size_t)MTOT * CC];      // LN output (tf32-rounded)
__device__ float g_qkv[(size_t)MTOT * 3 * CC];  // QKV GEMM output (fp32)
__device__ float g_att[(size_t)MTOT * CC];      // attention output (tf32-rounded)
__device__ float g_act[(size_t)MTOT * HID];     // gelu(fc1) (tf32-rounded)
__device__ float g_wq [(size_t)3 * CC * CC];    // tf32-rounded weights
__device__ float g_wp [(size_t)CC * CC];
__device__ float g_w1 [(size_t)HID * CC];
__device__ float g_w2 [(size_t)CC * HID];

// ---------------- helpers ---------------------------------------------------
__device__ __forceinline__ uint32_t f2tf32(float f) {
    uint32_t u;
    asm("cvt.rna.tf32.f32 %0, %1;" : "=r"(u) : "f"(f));
    return u;
}
__device__ __forceinline__ float rtf(float f) { return __uint_as_float(f2tf32(f)); }

__device__ __forceinline__ void mma_tf32(float c[4], const uint32_t a[4], const uint32_t b[2]) {
    asm volatile(
        "mma.sync.aligned.m16n8k8.row.col.f32.tf32.tf32.f32 "
        "{%0,%1,%2,%3}, {%4,%5,%6,%7}, {%8,%9}, {%0,%1,%2,%3};\n"
        : "+f"(c[0]), "+f"(c[1]), "+f"(c[2]), "+f"(c[3])
        : "r"(a[0]), "r"(a[1]), "r"(a[2]), "r"(a[3]), "r"(b[0]), "r"(b[1]));
}

__device__ __forceinline__ float gelu_tanh(float x) {
    float x3 = x * x * x;
    return 0.5f * x * (1.0f + tanhf(0.7978845608028654f * (x + 0.044715f * x3)));
}

__device__ __forceinline__ uint32_t smem_u32(const void* p) {
    uint32_t a;
    asm("{ .reg .u64 t; cvta.to.shared.u64 t, %1; cvt.u32.u64 %0, t; }" : "=r"(a) : "l"(p));
    return a;
}

__device__ __forceinline__ void cpasync16(uint32_t dst, const void* src) {
    asm volatile("cp.async.cg.shared.global [%0], [%1], 16;" :: "r"(dst), "l"(src));
}

// ---------------- tf32 weight rounding (prep) --------------------------------
__global__ __launch_bounds__(256)
void round_w(const float4* __restrict__ s, float4* __restrict__ d, int n4) {
    int i = blockIdx.x * blockDim.x + threadIdx.x;
    int stride = gridDim.x * blockDim.x;
    for (; i < n4; i += stride) {
        float4 v = s[i];
        v.x = rtf(v.x); v.y = rtf(v.y); v.z = rtf(v.z); v.w = rtf(v.w);
        d[i] = v;
    }
}

// ---------------- LayerNorm (tf32-rounded output) ----------------------------
__global__ __launch_bounds__(256)
void ln_kernel(const float* __restrict__ x, const float* __restrict__ g,
               const float* __restrict__ b, float* __restrict__ y) {
    int row = blockIdx.x;
    const float4* xr = (const float4*)(x + (size_t)row * CC);
    float4 v = xr[threadIdx.x];
    float s1 = v.x + v.y + v.z + v.w;
    float s2 = v.x * v.x + v.y * v.y + v.z * v.z + v.w * v.w;
    #pragma unroll
    for (int o = 16; o; o >>= 1) {
        s1 += __shfl_xor_sync(0xffffffffu, s1, o);
        s2 += __shfl_xor_sync(0xffffffffu, s2, o);
    }
    __shared__ float r1[8], r2[8];
    int w = threadIdx.x >> 5;
    if ((threadIdx.x & 31) == 0) { r1[w] = s1; r2[w] = s2; }
    __syncthreads();
    s1 = 0.f; s2 = 0.f;
    #pragma unroll
    for (int i = 0; i < 8; i++) { s1 += r1[i]; s2 += r2[i]; }
    float mu  = s1 * (1.0f / CC);
    float var = s2 * (1.0f / CC) - mu * mu;
    float rs  = rsqrtf(var + 1e-5f);
    float4 gv = ((const float4*)g)[threadIdx.x];
    float4 bv = ((const float4*)b)[threadIdx.x];
    float4 o;
    o.x = rtf((v.x - mu) * rs * gv.x + bv.x);
    o.y = rtf((v.y - mu) * rs * gv.y + bv.y);
    o.z = rtf((v.z - mu) * rs * gv.z + bv.z);
    o.w = rtf((v.w - mu) * rs * gv.w + bv.w);
    ((float4*)(y + (size_t)row * CC))[threadIdx.x] = o;
}

// ---------------- TF32 mma.sync GEMM:  out = A[M,K] @ W[N,K]^T + epi --------
// CTA 128(M) x 256(N) x 32(K-chunk); 8 warps as 2(M) x 4(N), warp tile 64x64
// (4x8 m16n8k8 tiles). 3-stage cp.async pipeline. Smem rows: 32 floats padded
// to 36 words (144B) -> fragment LDS banks (4g + t): conflict-free.
enum { EPI_BIAS = 0, EPI_RES = 1, EPI_GELU = 2 };

#define RSTRIDE     36
#define STAGE_ROWS  384                          // 128 A rows + 256 B rows
#define STAGE_BYTES (STAGE_ROWS * RSTRIDE * 4)   // 55296
#define NSTAGE      3
#define GSMEM_TOTAL (NSTAGE * STAGE_BYTES)       // 165888

template <int EPI>
__global__ __launch_bounds__(256, 1)
void gemm_tf32(const float* __restrict__ A, const float* __restrict__ W,
               const float* __restrict__ bias, const float* __restrict__ res,
               float* __restrict__ out, int K, int N) {
    extern __shared__ __align__(256) char smem_raw[];
    uint32_t sbase = smem_u32(smem_raw);
    uint32_t* sw = (uint32_t*)smem_raw;

    int tid = threadIdx.x, w = tid >> 5, lane = tid & 31;
    int g = lane >> 2, t = lane & 3;
    int bm = blockIdx.y * 128, bn = blockIdx.x * 256;
    int wm = (w & 1) * 64, wn = (w >> 1) * 64;

    const int nk = K >> 5;

    // chunk mapping for loads: 3072 16B-chunks per stage, 12 per thread
    auto load_stage = [&](int s, int k0) {
        uint32_t sb = sbase + s * STAGE_BYTES;
        #pragma unroll
        for (int i = 0; i < 12; i++) {
            int c = tid + 256 * i;
            int row = c >> 3, kq = c & 7;
            const float* src = (row < 128)
                ? (A + (size_t)(bm + row) * K + k0 + kq * 4)
                : (W + (size_t)(bn + row - 128) * K + k0 + kq * 4);
            cpasync16(sb + row * (RSTRIDE * 4) + kq * 16, src);
        }
        asm volatile("cp.async.commit_group;" ::: "memory");
    };

    float acc[4][8][4];
    #pragma unroll
    for (int mt = 0; mt < 4; mt++)
        #pragma unroll
        for (int nt = 0; nt < 8; nt++)
            #pragma unroll
            for (int q = 0; q < 4; q++) acc[mt][nt][q] = 0.f;

    load_stage(0, 0);
    load_stage(1, 32);

    for (int kt = 0; kt < nk; kt++) {
        asm volatile("cp.async.wait_group 1;" ::: "memory");
        __syncthreads();
        if (kt + 2 < nk) load_stage((kt + 2) % NSTAGE, (kt + 2) * 32);
        else { asm volatile("cp.async.commit_group;" ::: "memory"); }

        const uint32_t* As = sw + ((kt % NSTAGE) * STAGE_ROWS) * RSTRIDE;
        const uint32_t* Bs = As + 128 * RSTRIDE;

        #pragma unroll
        for (int kk = 0; kk < 32; kk += 8) {
            uint32_t af[4][4];
            #pragma unroll
            for (int mt = 0; mt < 4; mt++) {
                int r0 = wm + mt * 16 + g;
                af[mt][0] = As[r0 * RSTRIDE + kk + t];
                af[mt][1] = As[(r0 + 8) * RSTRIDE + kk + t];
                af[mt][2] = As[r0 * RSTRIDE + kk + t + 4];
                af[mt][3] = As[(r0 + 8) * RSTRIDE + kk + t + 4];
            }
            uint32_t bf[8][2];
            #pragma unroll
            for (int nt = 0; nt < 8; nt++) {
                int c0 = wn + nt * 8 + g;
                bf[nt][0] = Bs[c0 * RSTRIDE + kk + t];
                bf[nt][1] = Bs[c0 * RSTRIDE + kk + t + 4];
            }
            #pragma unroll
            for (int mt = 0; mt < 4; mt++)
                #pragma unroll
                for (int nt = 0; nt < 8; nt++)
                    mma_tf32(acc[mt][nt], af[mt], bf[nt]);
        }
        __syncthreads();
    }

    // epilogue
    #pragma unroll
    for (int mt = 0; mt < 4; mt++) {
        #pragma unroll
        for (int nt = 0; nt < 8; nt++) {
            int rr0 = bm + wm + mt * 16 + g;
            int cc  = bn + wn + nt * 8 + 2 * t;
            float b0 = bias[cc], b1 = bias[cc + 1];
            #pragma unroll
            for (int hh = 0; hh < 2; hh++) {
                int rr = rr0 + hh * 8;
                float v0 = acc[mt][nt][hh * 2 + 0] + b0;
                float v1 = acc[mt][nt][hh * 2 + 1] + b1;
                if (EPI == EPI_RES) {
                    float2 rv = *(const float2*)(res + (size_t)rr * N + cc);
                    v0 += rv.x; v1 += rv.y;
                }
                if (EPI == EPI_GELU) {
                    v0 = rtf(gelu_tanh(v0));
                    v1 = rtf(gelu_tanh(v1));
                }
                *(float2*)(out + (size_t)rr * N + cc) = make_float2(v0, v1);
            }
        }
    }
}

// ---------------- Attention: one block per (b,h), fp32 SIMT -----------------
__global__ __launch_bounds__(128)
void attn_kernel(const float* __restrict__ qkv, const float* __restrict__ abias,
                 const float* __restrict__ bscale_p, float* __restrict__ out) {
    __shared__ float sq[65 * 65];
    __shared__ float skv[65 * 65];

    int bh = blockIdx.x;
    int b  = bh >> 4, h = bh & 15;
    int tid = threadIdx.x;
    size_t base = (size_t)b * SEQ * 3072 + (size_t)h * 64;

    for (int idx = tid; idx < 65 * 64; idx += 128) {
        int n = idx >> 6, d = idx & 63;
        size_t gsrc = base + (size_t)n * 3072 + d;
        sq [n * 65 + d] = qkv[gsrc];
        skv[n * 65 + d] = qkv[gsrc + 1024];
    }
    __syncthreads();

    float bsc = *bscale_p;
    int ty = tid >> 3, tx = tid & 7;

    float acc[5][9];
    #pragma unroll
    for (int i = 0; i < 5; i++)
        #pragma unroll
        for (int j = 0; j < 9; j++) acc[i][j] = 0.f;

    for (int d = 0; d < 64; d++) {
        float qv[5], kv[9];
        #pragma unroll
        for (int i = 0; i < 5; i++) {
            int n = ty + 16 * i; if (n > 64) n = 64;
            qv[i] = sq[n * 65 + d];
        }
        #pragma unroll
        for (int j = 0; j < 9; j++) {
            int m = tx + 8 * j; if (m > 64) m = 64;
            kv[j] = skv[m * 65 + d];
        }
        #pragma unroll
        for (int i = 0; i < 5; i++)
            #pragma unroll
            for (int j = 0; j < 9; j++)
                acc[i][j] += qv[i] * kv[j];
    }

    const float NEG = -1e30f;
    #pragma unroll
    for (int i = 0; i < 5; i++) {
        int n = ty + 16 * i;
        bool valid = (n <= 64);
        int nc = valid ? n : 64;
        const float* brow = abias + ((size_t)h * 65 + nc) * 65;

        float l[9];
        float mx = NEG;
        #pragma unroll
        for (int j = 0; j < 9; j++) {
            int m = tx + 8 * j;
            float lv = NEG;
            if (valid && m <= 64) lv = acc[i][j] * 0.125f + bsc * brow[m];
            l[j] = lv;
            mx = fmaxf(mx, lv);
        }
        mx = fmaxf(mx, __shfl_xor_sync(0xffffffffu, mx, 1));
        mx = fmaxf(mx, __shfl_xor_sync(0xffffffffu, mx, 2));
        mx = fmaxf(mx, __shfl_xor_sync(0xffffffffu, mx, 4));
        float s = 0.f;
        #pragma unroll
        for (int j = 0; j < 9; j++) { l[j] = __expf(l[j] - mx); s += l[j]; }
        s += __shfl_xor_sync(0xffffffffu, s, 1);
        s += __shfl_xor_sync(0xffffffffu, s, 2);
        s += __shfl_xor_sync(0xffffffffu, s, 4);
        float inv = 1.0f / s;
        #pragma unroll
        for (int j = 0; j < 9; j++) {
            int m = tx + 8 * j;
            if (valid && m <= 64) sq[n * 65 + m] = l[j] * inv;
        }
    }
    __syncthreads();

    for (int idx = tid; idx < 65 * 64; idx += 128) {
        int n = idx >> 6, d = idx & 63;
        skv[n * 65 + d] = qkv[base + (size_t)n * 3072 + d + 2048];
    }
    __syncthreads();

    float acc2[5][8];
    #pragma unroll
    for (int i = 0; i < 5; i++)
        #pragma unroll
        for (int j = 0; j < 8; j++) acc2[i][j] = 0.f;

    for (int m = 0; m <= 64; m++) {
        float pv[5], vv[8];
        #pragma unroll
        for (int i = 0; i < 5; i++) {
            int n = ty + 16 * i; if (n > 64) n = 64;
            pv[i] = sq[n * 65 + m];
        }
        #pragma unroll
        for (int j = 0; j < 8; j++)
            vv[j] = skv[m * 65 + tx + 8 * j];
        #pragma unroll
        for (int i = 0; i < 5; i++)
            #pragma unroll
            for (int j = 0; j < 8; j++)
                acc2[i][j] += pv[i] * vv[j];
    }

    size_t obase = (size_t)b * SEQ * 1024 + (size_t)h * 64;
    #pragma unroll
    for (int i = 0; i < 5; i++) {
        int n = ty + 16 * i;
        if (n <= 64) {
            #pragma unroll
            for (int j = 0; j < 8; j++)
                out[obase + (size_t)n * 1024 + tx + 8 * j] = rtf(acc2[i][j]);
        }
    }
}

// ---------------- launch -----------------------------------------------------
extern "C" void kernel_launch(void* const* d_in, const int* in_sizes, int n_in,
                              void* d_out, int out_size) {
    const float* x        = (const float*)d_in[0];
    const float* ln1_g    = (const float*)d_in[1];
    const float* ln1_b    = (const float*)d_in[2];
    const float* qkv_w    = (const float*)d_in[3];
    const float* qkv_b    = (const float*)d_in[4];
    const float* proj_w   = (const float*)d_in[5];
    const float* proj_b   = (const float*)d_in[6];
    const float* attnbias = (const float*)d_in[7];
    const float* bscale   = (const float*)d_in[8];
    const float* ln2_g    = (const float*)d_in[9];
    const float* ln2_b    = (const float*)d_in[10];
    const float* fc1_w    = (const float*)d_in[11];
    const float* fc1_b    = (const float*)d_in[12];
    const float* fc2_w    = (const float*)d_in[13];
    const float* fc2_b    = (const float*)d_in[14];
    float* out = (float*)d_out;

    float *h, *qkv, *att, *act, *wq, *wp, *w1, *w2;
    cudaGetSymbolAddress((void**)&h,   g_h);
    cudaGetSymbolAddress((void**)&qkv, g_qkv);
    cudaGetSymbolAddress((void**)&att, g_att);
    cudaGetSymbolAddress((void**)&act, g_act);
    cudaGetSymbolAddress((void**)&wq,  g_wq);
    cudaGetSymbolAddress((void**)&wp,  g_wp);
    cudaGetSymbolAddress((void**)&w1,  g_w1);
    cudaGetSymbolAddress((void**)&w2,  g_w2);

    cudaFuncSetAttribute(gemm_tf32<EPI_BIAS>, cudaFuncAttributeMaxDynamicSharedMemorySize, GSMEM_TOTAL);
    cudaFuncSetAttribute(gemm_tf32<EPI_RES>,  cudaFuncAttributeMaxDynamicSharedMemorySize, GSMEM_TOTAL);
    cudaFuncSetAttribute(gemm_tf32<EPI_GELU>, cudaFuncAttributeMaxDynamicSharedMemorySize, GSMEM_TOTAL);

    // 0. tf32-round weights into scratch
    round_w<<<512, 256>>>((const float4*)qkv_w,  (float4*)wq, 3 * CC * CC / 4);
    round_w<<<512, 256>>>((const float4*)proj_w, (float4*)wp, CC * CC / 4);
    round_w<<<512, 256>>>((const float4*)fc1_w,  (float4*)w1, HID * CC / 4);
    round_w<<<512, 256>>>((const float4*)fc2_w,  (float4*)w2, CC * HID / 4);

    // 1. h = LN1(x)   (tf32-rounded)
    ln_kernel<<<MTOT, 256>>>(x, ln1_g, ln1_b, h);
    // 2. qkv = h @ qkv_w^T + qkv_b
    gemm_tf32<EPI_BIAS><<<dim3(3 * CC / 256, MTOT / 128), 256, GSMEM_TOTAL>>>(
        h, wq, qkv_b, nullptr, qkv, CC, 3 * CC);
    // 3. attention -> att (tf32-rounded)
    attn_kernel<<<BB * HH, 128>>>(qkv, attnbias, bscale, att);
    // 4. out = x + att @ proj_w^T + proj_b
    gemm_tf32<EPI_RES><<<dim3(CC / 256, MTOT / 128), 256, GSMEM_TOTAL>>>(
        att, wp, proj_b, x, out, CC, CC);
    // 5. h = LN2(out)
    ln_kernel<<<MTOT, 256>>>(out, ln2_g, ln2_b, h);
    // 6. act = gelu(h @ fc1_w^T + fc1_b)  (tf32-rounded)
    gemm_tf32<EPI_GELU><<<dim3(HID / 256, MTOT / 128), 256, GSMEM_TOTAL>>>(
        h, w1, fc1_b, nullptr, act, CC, HID);
    // 7. out = out + act @ fc2_w^T + fc2_b
    gemm_tf32<EPI_RES><<<dim3(CC / 256, MTOT / 128), 256, GSMEM_TOTAL>>>(
        act, w2, fc2_b, out, out, HID, CC);
}

// round 4
// speedup vs baseline: 1.4475x; 1.0701x over previous
#include <cuda_runtime.h>
#include <cstdint>
#include <math.h>

#define BB   1024
#define SEQ  65
#define CC   1024
#define HH   16
#define HID  4096
#define MTOT (BB*SEQ)   // 66560 = 520 * 128

// ---------------- scratch (device globals: no allocations allowed) ----------
__device__ float g_h  [(size_t)MTOT * CC];      // LN output (tf32-rounded)
__device__ float g_qkv[(size_t)MTOT * 3 * CC];  // QKV GEMM output (fp32)
__device__ float g_att[(size_t)MTOT * CC];      // attention output (tf32-rounded)
__device__ float g_act[(size_t)MTOT * HID];     // gelu(fc1) (tf32-rounded)
__device__ float g_wq [(size_t)3 * CC * CC];    // tf32-rounded weights
__device__ float g_wp [(size_t)CC * CC];
__device__ float g_w1 [(size_t)HID * CC];
__device__ float g_w2 [(size_t)CC * HID];

// ---------------- helpers ---------------------------------------------------
__device__ __forceinline__ uint32_t f2tf32(float f) {
    uint32_t u;
    asm("cvt.rna.tf32.f32 %0, %1;" : "=r"(u) : "f"(f));
    return u;
}
__device__ __forceinline__ float rtf(float f) { return __uint_as_float(f2tf32(f)); }

__device__ __forceinline__ void mma_tf32(float c[4], const uint32_t a[4], const uint32_t b[2]) {
    asm volatile(
        "mma.sync.aligned.m16n8k8.row.col.f32.tf32.tf32.f32 "
        "{%0,%1,%2,%3}, {%4,%5,%6,%7}, {%8,%9}, {%0,%1,%2,%3};\n"
        : "+f"(c[0]), "+f"(c[1]), "+f"(c[2]), "+f"(c[3])
        : "r"(a[0]), "r"(a[1]), "r"(a[2]), "r"(a[3]), "r"(b[0]), "r"(b[1]));
}

__device__ __forceinline__ float gelu_tanh(float x) {
    float x3 = x * x * x;
    return 0.5f * x * (1.0f + tanhf(0.7978845608028654f * (x + 0.044715f * x3)));
}

__device__ __forceinline__ uint32_t smem_u32(const void* p) {
    uint32_t a;
    asm("{ .reg .u64 t; cvta.to.shared.u64 t, %1; cvt.u32.u64 %0, t; }" : "=r"(a) : "l"(p));
    return a;
}

__device__ __forceinline__ void cpasync16(uint32_t dst, const void* src) {
    asm volatile("cp.async.cg.shared.global [%0], [%1], 16;" :: "r"(dst), "l"(src));
}

// ---------------- tf32 weight rounding (prep) --------------------------------
__global__ __launch_bounds__(256)
void round_w(const float4* __restrict__ s, float4* __restrict__ d, int n4) {
    int i = blockIdx.x * blockDim.x + threadIdx.x;
    int stride = gridDim.x * blockDim.x;
    for (; i < n4; i += stride) {
        float4 v = s[i];
        v.x = rtf(v.x); v.y = rtf(v.y); v.z = rtf(v.z); v.w = rtf(v.w);
        d[i] = v;
    }
}

// ---------------- LayerNorm (tf32-rounded output) ----------------------------
__global__ __launch_bounds__(256)
void ln_kernel(const float* __restrict__ x, const float* __restrict__ g,
               const float* __restrict__ b, float* __restrict__ y) {
    int row = blockIdx.x;
    const float4* xr = (const float4*)(x + (size_t)row * CC);
    float4 v = xr[threadIdx.x];
    float s1 = v.x + v.y + v.z + v.w;
    float s2 = v.x * v.x + v.y * v.y + v.z * v.z + v.w * v.w;
    #pragma unroll
    for (int o = 16; o; o >>= 1) {
        s1 += __shfl_xor_sync(0xffffffffu, s1, o);
        s2 += __shfl_xor_sync(0xffffffffu, s2, o);
    }
    __shared__ float r1[8], r2[8];
    int w = threadIdx.x >> 5;
    if ((threadIdx.x & 31) == 0) { r1[w] = s1; r2[w] = s2; }
    __syncthreads();
    s1 = 0.f; s2 = 0.f;
    #pragma unroll
    for (int i = 0; i < 8; i++) { s1 += r1[i]; s2 += r2[i]; }
    float mu  = s1 * (1.0f / CC);
    float var = s2 * (1.0f / CC) - mu * mu;
    float rs  = rsqrtf(var + 1e-5f);
    float4 gv = ((const float4*)g)[threadIdx.x];
    float4 bv = ((const float4*)b)[threadIdx.x];
    float4 o;
    o.x = rtf((v.x - mu) * rs * gv.x + bv.x);
    o.y = rtf((v.y - mu) * rs * gv.y + bv.y);
    o.z = rtf((v.z - mu) * rs * gv.z + bv.z);
    o.w = rtf((v.w - mu) * rs * gv.w + bv.w);
    ((float4*)(y + (size_t)row * CC))[threadIdx.x] = o;
}

// ---------------- TF32 mma.sync GEMM:  out = A[M,K] @ W[N,K]^T + epi --------
// CTA 128(M) x 256(N) x 32(K-chunk); 8 warps as 2(M) x 4(N), warp tile 64x64.
// 3-stage cp.async pipeline. Smem rows: 32 floats padded to 40 words (160B).
// Fragment loads are LDS.64: logical-k permutation (mma k-lane t <- smem words
// o+2t, o+2t+1, identically for A and B) makes pairs contiguous; with stride 40
// phase banks are 8g+2t+{0,1} -> all 32 banks exactly once: conflict-free.
enum { EPI_BIAS = 0, EPI_RES = 1, EPI_GELU = 2 };

#define RSTRIDE     40
#define STAGE_ROWS  384                          // 128 A rows + 256 B rows
#define STAGE_BYTES (STAGE_ROWS * RSTRIDE * 4)   // 61440
#define NSTAGE      3
#define GSMEM_TOTAL (NSTAGE * STAGE_BYTES)       // 184320

template <int EPI>
__global__ __launch_bounds__(256, 1)
void gemm_tf32(const float* __restrict__ A, const float* __restrict__ W,
               const float* __restrict__ bias, const float* __restrict__ res,
               float* __restrict__ out, int K, int N) {
    extern __shared__ __align__(256) char smem_raw[];
    uint32_t sbase = smem_u32(smem_raw);
    uint32_t* sw = (uint32_t*)smem_raw;

    int tid = threadIdx.x, w = tid >> 5, lane = tid & 31;
    int g = lane >> 2, t = lane & 3;
    int bm = blockIdx.y * 128, bn = blockIdx.x * 256;
    int wm = (w & 1) * 64, wn = (w >> 1) * 64;

    const int nk = K >> 5;

    auto load_stage = [&](int s, int k0) {
        uint32_t sb = sbase + s * STAGE_BYTES;
        #pragma unroll
        for (int i = 0; i < 12; i++) {
            int c = tid + 256 * i;
            int row = c >> 3, kq = c & 7;
            const float* src = (row < 128)
                ? (A + (size_t)(bm + row) * K + k0 + kq * 4)
                : (W + (size_t)(bn + row - 128) * K + k0 + kq * 4);
            cpasync16(sb + row * (RSTRIDE * 4) + kq * 16, src);
        }
        asm volatile("cp.async.commit_group;" ::: "memory");
    };

    float acc[4][8][4];
    #pragma unroll
    for (int mt = 0; mt < 4; mt++)
        #pragma unroll
        for (int nt = 0; nt < 8; nt++)
            #pragma unroll
            for (int q = 0; q < 4; q++) acc[mt][nt][q] = 0.f;

    load_stage(0, 0);
    load_stage(1, 32);

    for (int kt = 0; kt < nk; kt++) {
        asm volatile("cp.async.wait_group 1;" ::: "memory");
        __syncthreads();
        if (kt + 2 < nk) load_stage((kt + 2) % NSTAGE, (kt + 2) * 32);
        else { asm volatile("cp.async.commit_group;" ::: "memory"); }

        const uint32_t* As = sw + ((kt % NSTAGE) * STAGE_ROWS) * RSTRIDE;
        const uint32_t* Bs = As + 128 * RSTRIDE;

        #pragma unroll
        for (int kk = 0; kk < 32; kk += 8) {
            // LDS.64 fragment loads; logical k-lane t <-> global k kk+2t, kk+2t+1
            uint32_t af[4][4];
            #pragma unroll
            for (int mt = 0; mt < 4; mt++) {
                int r0 = wm + mt * 16 + g;
                uint2 lo = *(const uint2*)&As[r0 * RSTRIDE + kk + 2 * t];
                uint2 hi = *(const uint2*)&As[(r0 + 8) * RSTRIDE + kk + 2 * t];
                af[mt][0] = lo.x; af[mt][2] = lo.y;
                af[mt][1] = hi.x; af[mt][3] = hi.y;
            }
            uint32_t bf[8][2];
            #pragma unroll
            for (int nt = 0; nt < 8; nt++) {
                int c0 = wn + nt * 8 + g;
                uint2 bb = *(const uint2*)&Bs[c0 * RSTRIDE + kk + 2 * t];
                bf[nt][0] = bb.x; bf[nt][1] = bb.y;
            }
            #pragma unroll
            for (int mt = 0; mt < 4; mt++)
                #pragma unroll
                for (int nt = 0; nt < 8; nt++)
                    mma_tf32(acc[mt][nt], af[mt], bf[nt]);
        }
        // no trailing __syncthreads: stage (kt%3) is only rewritten at iter
        // kt+1's load_stage, which happens after iter kt+1's top barrier.
    }

    // epilogue
    #pragma unroll
    for (int mt = 0; mt < 4; mt++) {
        #pragma unroll
        for (int nt = 0; nt < 8; nt++) {
            int rr0 = bm + wm + mt * 16 + g;
            int cc  = bn + wn + nt * 8 + 2 * t;
            float b0 = bias[cc], b1 = bias[cc + 1];
            #pragma unroll
            for (int hh = 0; hh < 2; hh++) {
                int rr = rr0 + hh * 8;
                float v0 = acc[mt][nt][hh * 2 + 0] + b0;
                float v1 = acc[mt][nt][hh * 2 + 1] + b1;
                if (EPI == EPI_RES) {
                    float2 rv = *(const float2*)(res + (size_t)rr * N + cc);
                    v0 += rv.x; v1 += rv.y;
                }
                if (EPI == EPI_GELU) {
                    v0 = rtf(gelu_tanh(v0));
                    v1 = rtf(gelu_tanh(v1));
                }
                *(float2*)(out + (size_t)rr * N + cc) = make_float2(v0, v1);
            }
        }
    }
}

// ---------------- Attention: one block per (b,h), fp32 SIMT -----------------
__global__ __launch_bounds__(128)
void attn_kernel(const float* __restrict__ qkv, const float* __restrict__ abias,
                 const float* __restrict__ bscale_p, float* __restrict__ out) {
    __shared__ float sq[65 * 65];
    __shared__ float skv[65 * 65];

    int bh = blockIdx.x;
    int b  = bh >> 4, h = bh & 15;
    int tid = threadIdx.x;
    size_t base = (size_t)b * SEQ * 3072 + (size_t)h * 64;

    for (int idx = tid; idx < 65 * 64; idx += 128) {
        int n = idx >> 6, d = idx & 63;
        size_t gsrc = base + (size_t)n * 3072 + d;
        sq [n * 65 + d] = qkv[gsrc];
        skv[n * 65 + d] = qkv[gsrc + 1024];
    }
    __syncthreads();

    float bsc = *bscale_p;
    int ty = tid >> 3, tx = tid & 7;

    float acc[5][9];
    #pragma unroll
    for (int i = 0; i < 5; i++)
        #pragma unroll
        for (int j = 0; j < 9; j++) acc[i][j] = 0.f;

    for (int d = 0; d < 64; d++) {
        float qv[5], kv[9];
        #pragma unroll
        for (int i = 0; i < 5; i++) {
            int n = ty + 16 * i; if (n > 64) n = 64;
            qv[i] = sq[n * 65 + d];
        }
        #pragma unroll
        for (int j = 0; j < 9; j++) {
            int m = tx + 8 * j; if (m > 64) m = 64;
            kv[j] = skv[m * 65 + d];
        }
        #pragma unroll
        for (int i = 0; i < 5; i++)
            #pragma unroll
            for (int j = 0; j < 9; j++)
                acc[i][j] += qv[i] * kv[j];
    }

    const float NEG = -1e30f;
    #pragma unroll
    for (int i = 0; i < 5; i++) {
        int n = ty + 16 * i;
        bool valid = (n <= 64);
        int nc = valid ? n : 64;
        const float* brow = abias + ((size_t)h * 65 + nc) * 65;

        float l[9];
        float mx = NEG;
        #pragma unroll
        for (int j = 0; j < 9; j++) {
            int m = tx + 8 * j;
            float lv = NEG;
            if (valid && m <= 64) lv = acc[i][j] * 0.125f + bsc * brow[m];
            l[j] = lv;
            mx = fmaxf(mx, lv);
        }
        mx = fmaxf(mx, __shfl_xor_sync(0xffffffffu, mx, 1));
        mx = fmaxf(mx, __shfl_xor_sync(0xffffffffu, mx, 2));
        mx = fmaxf(mx, __shfl_xor_sync(0xffffffffu, mx, 4));
        float s = 0.f;
        #pragma unroll
        for (int j = 0; j < 9; j++) { l[j] = __expf(l[j] - mx); s += l[j]; }
        s += __shfl_xor_sync(0xffffffffu, s, 1);
        s += __shfl_xor_sync(0xffffffffu, s, 2);
        s += __shfl_xor_sync(0xffffffffu, s, 4);
        float inv = 1.0f / s;
        #pragma unroll
        for (int j = 0; j < 9; j++) {
            int m = tx + 8 * j;
            if (valid && m <= 64) sq[n * 65 + m] = l[j] * inv;
        }
    }
    __syncthreads();

    for (int idx = tid; idx < 65 * 64; idx += 128) {
        int n = idx >> 6, d = idx & 63;
        skv[n * 65 + d] = qkv[base + (size_t)n * 3072 + d + 2048];
    }
    __syncthreads();

    float acc2[5][8];
    #pragma unroll
    for (int i = 0; i < 5; i++)
        #pragma unroll
        for (int j = 0; j < 8; j++) acc2[i][j] = 0.f;

    for (int m = 0; m <= 64; m++) {
        float pv[5], vv[8];
        #pragma unroll
        for (int i = 0; i < 5; i++) {
            int n = ty + 16 * i; if (n > 64) n = 64;
            pv[i] = sq[n * 65 + m];
        }
        #pragma unroll
        for (int j = 0; j < 8; j++)
            vv[j] = skv[m * 65 + tx + 8 * j];
        #pragma unroll
        for (int i = 0; i < 5; i++)
            #pragma unroll
            for (int j = 0; j < 8; j++)
                acc2[i][j] += pv[i] * vv[j];
    }

    size_t obase = (size_t)b * SEQ * 1024 + (size_t)h * 64;
    #pragma unroll
    for (int i = 0; i < 5; i++) {
        int n = ty + 16 * i;
        if (n <= 64) {
            #pragma unroll
            for (int j = 0; j < 8; j++)
                out[obase + (size_t)n * 1024 + tx + 8 * j] = rtf(acc2[i][j]);
        }
    }
}

// ---------------- launch -----------------------------------------------------
extern "C" void kernel_launch(void* const* d_in, const int* in_sizes, int n_in,
                              void* d_out, int out_size) {
    const float* x        = (const float*)d_in[0];
    const float* ln1_g    = (const float*)d_in[1];
    const float* ln1_b    = (const float*)d_in[2];
    const float* qkv_w    = (const float*)d_in[3];
    const float* qkv_b    = (const float*)d_in[4];
    const float* proj_w   = (const float*)d_in[5];
    const float* proj_b   = (const float*)d_in[6];
    const float* attnbias = (const float*)d_in[7];
    const float* bscale   = (const float*)d_in[8];
    const float* ln2_g    = (const float*)d_in[9];
    const float* ln2_b    = (const float*)d_in[10];
    const float* fc1_w    = (const float*)d_in[11];
    const float* fc1_b    = (const float*)d_in[12];
    const float* fc2_w    = (const float*)d_in[13];
    const float* fc2_b    = (const float*)d_in[14];
    float* out = (float*)d_out;

    float *h, *qkv, *att, *act, *wq, *wp, *w1, *w2;
    cudaGetSymbolAddress((void**)&h,   g_h);
    cudaGetSymbolAddress((void**)&qkv, g_qkv);
    cudaGetSymbolAddress((void**)&att, g_att);
    cudaGetSymbolAddress((void**)&act, g_act);
    cudaGetSymbolAddress((void**)&wq,  g_wq);
    cudaGetSymbolAddress((void**)&wp,  g_wp);
    cudaGetSymbolAddress((void**)&w1,  g_w1);
    cudaGetSymbolAddress((void**)&w2,  g_w2);

    cudaFuncSetAttribute(gemm_tf32<EPI_BIAS>, cudaFuncAttributeMaxDynamicSharedMemorySize, GSMEM_TOTAL);
    cudaFuncSetAttribute(gemm_tf32<EPI_RES>,  cudaFuncAttributeMaxDynamicSharedMemorySize, GSMEM_TOTAL);
    cudaFuncSetAttribute(gemm_tf32<EPI_GELU>, cudaFuncAttributeMaxDynamicSharedMemorySize, GSMEM_TOTAL);

    // 0. tf32-round weights into scratch
    round_w<<<512, 256>>>((const float4*)qkv_w,  (float4*)wq, 3 * CC * CC / 4);
    round_w<<<512, 256>>>((const float4*)proj_w, (float4*)wp, CC * CC / 4);
    round_w<<<512, 256>>>((const float4*)fc1_w,  (float4*)w1, HID * CC / 4);
    round_w<<<512, 256>>>((const float4*)fc2_w,  (float4*)w2, CC * HID / 4);

    // 1. h = LN1(x)   (tf32-rounded)
    ln_kernel<<<MTOT, 256>>>(x, ln1_g, ln1_b, h);
    // 2. qkv = h @ qkv_w^T + qkv_b
    gemm_tf32<EPI_BIAS><<<dim3(3 * CC / 256, MTOT / 128), 256, GSMEM_TOTAL>>>(
        h, wq, qkv_b, nullptr, qkv, CC, 3 * CC);
    // 3. attention -> att (tf32-rounded)
    attn_kernel<<<BB * HH, 128>>>(qkv, attnbias, bscale, att);
    // 4. out = x + att @ proj_w^T + proj_b
    gemm_tf32<EPI_RES><<<dim3(CC / 256, MTOT / 128), 256, GSMEM_TOTAL>>>(
        att, wp, proj_b, x, out, CC, CC);
    // 5. h = LN2(out)
    ln_kernel<<<MTOT, 256>>>(out, ln2_g, ln2_b, h);
    // 6. act = gelu(h @ fc1_w^T + fc1_b)  (tf32-rounded)
    gemm_tf32<EPI_GELU><<<dim3(HID / 256, MTOT / 128), 256, GSMEM_TOTAL>>>(
        h, w1, fc1_b, nullptr, act, CC, HID);
    // 7. out = out + act @ fc2_w^T + fc2_b
    gemm_tf32<EPI_RES><<<dim3(CC / 256, MTOT / 128), 256, GSMEM_TOTAL>>>(
        act, w2, fc2_b, out, out, HID, CC);
}

// round 5
// speedup vs baseline: 1.5278x; 1.0554x over previous
#include <cuda_runtime.h>
#include <cstdint>
#include <math.h>

#define BB   1024
#define SEQ  65
#define CC   1024
#define HH   16
#define HID  4096
#define MTOT (BB*SEQ)   // 66560 = 520 * 128

// ---------------- scratch (device globals: no allocations allowed) ----------
__device__ float g_h  [(size_t)MTOT * CC];      // LN output (tf32-rounded)
__device__ float g_qkv[(size_t)MTOT * 3 * CC];  // QKV GEMM output (fp32)
__device__ float g_att[(size_t)MTOT * CC];      // attention output (tf32-rounded)
__device__ float g_act[(size_t)MTOT * HID];     // gelu(fc1) (tf32-rounded)
__device__ float g_wq [(size_t)3 * CC * CC];    // tf32-rounded weights
__device__ float g_wp [(size_t)CC * CC];
__device__ float g_w1 [(size_t)HID * CC];
__device__ float g_w2 [(size_t)CC * HID];

// ---------------- helpers ---------------------------------------------------
__device__ __forceinline__ uint32_t f2tf32(float f) {
    uint32_t u;
    asm("cvt.rna.tf32.f32 %0, %1;" : "=r"(u) : "f"(f));
    return u;
}
__device__ __forceinline__ float rtf(float f) { return __uint_as_float(f2tf32(f)); }

__device__ __forceinline__ void mma_tf32(float c[4], const uint32_t a[4], const uint32_t b[2]) {
    asm volatile(
        "mma.sync.aligned.m16n8k8.row.col.f32.tf32.tf32.f32 "
        "{%0,%1,%2,%3}, {%4,%5,%6,%7}, {%8,%9}, {%0,%1,%2,%3};\n"
        : "+f"(c[0]), "+f"(c[1]), "+f"(c[2]), "+f"(c[3])
        : "r"(a[0]), "r"(a[1]), "r"(a[2]), "r"(a[3]), "r"(b[0]), "r"(b[1]));
}

__device__ __forceinline__ float gelu_tanh(float x) {
    float x3 = x * x * x;
    return 0.5f * x * (1.0f + tanhf(0.7978845608028654f * (x + 0.044715f * x3)));
}

__device__ __forceinline__ uint32_t smem_u32(const void* p) {
    uint32_t a;
    asm("{ .reg .u64 t; cvta.to.shared.u64 t, %1; cvt.u32.u64 %0, t; }" : "=r"(a) : "l"(p));
    return a;
}

__device__ __forceinline__ void cpasync16(uint32_t dst, const void* src) {
    asm volatile("cp.async.cg.shared.global [%0], [%1], 16;" :: "r"(dst), "l"(src));
}

// ---------------- tf32 weight rounding (prep) --------------------------------
__global__ __launch_bounds__(256)
void round_w(const float4* __restrict__ s, float4* __restrict__ d, int n4) {
    int i = blockIdx.x * blockDim.x + threadIdx.x;
    int stride = gridDim.x * blockDim.x;
    for (; i < n4; i += stride) {
        float4 v = s[i];
        v.x = rtf(v.x); v.y = rtf(v.y); v.z = rtf(v.z); v.w = rtf(v.w);
        d[i] = v;
    }
}

// ---------------- LayerNorm (tf32-rounded output) ----------------------------
__global__ __launch_bounds__(256)
void ln_kernel(const float* __restrict__ x, const float* __restrict__ g,
               const float* __restrict__ b, float* __restrict__ y) {
    int row = blockIdx.x;
    const float4* xr = (const float4*)(x + (size_t)row * CC);
    float4 v = xr[threadIdx.x];
    float s1 = v.x + v.y + v.z + v.w;
    float s2 = v.x * v.x + v.y * v.y + v.z * v.z + v.w * v.w;
    #pragma unroll
    for (int o = 16; o; o >>= 1) {
        s1 += __shfl_xor_sync(0xffffffffu, s1, o);
        s2 += __shfl_xor_sync(0xffffffffu, s2, o);
    }
    __shared__ float r1[8], r2[8];
    int w = threadIdx.x >> 5;
    if ((threadIdx.x & 31) == 0) { r1[w] = s1; r2[w] = s2; }
    __syncthreads();
    s1 = 0.f; s2 = 0.f;
    #pragma unroll
    for (int i = 0; i < 8; i++) { s1 += r1[i]; s2 += r2[i]; }
    float mu  = s1 * (1.0f / CC);
    float var = s2 * (1.0f / CC) - mu * mu;
    float rs  = rsqrtf(var + 1e-5f);
    float4 gv = ((const float4*)g)[threadIdx.x];
    float4 bv = ((const float4*)b)[threadIdx.x];
    float4 o;
    o.x = rtf((v.x - mu) * rs * gv.x + bv.x);
    o.y = rtf((v.y - mu) * rs * gv.y + bv.y);
    o.z = rtf((v.z - mu) * rs * gv.z + bv.z);
    o.w = rtf((v.w - mu) * rs * gv.w + bv.w);
    ((float4*)(y + (size_t)row * CC))[threadIdx.x] = o;
}

// ---------------- TF32 mma.sync GEMM:  out = A[M,K] @ W[N,K]^T + epi --------
// CTA 128(M) x 128(N) x 32(K-chunk); 4 warps as 2x2, warp tile 64x64.
// 2-stage cp.async ring, 80KB smem -> 2 CTAs/SM: inter-CTA overlap hides
// barrier / epilogue bubbles. Rows padded to 40 words: LDS.64 fragment loads
// are conflict-free per 16-lane phase (banks 8g+2t+{0,1} cover all 32).
enum { EPI_BIAS = 0, EPI_RES = 1, EPI_GELU = 2 };

#define RSTRIDE     40
#define STAGE_ROWS  256                          // 128 A rows + 128 B rows
#define STAGE_BYTES (STAGE_ROWS * RSTRIDE * 4)   // 40960
#define NSTAGE      2
#define GSMEM_TOTAL (NSTAGE * STAGE_BYTES)       // 81920

template <int EPI>
__global__ __launch_bounds__(128, 2)
void gemm_tf32(const float* __restrict__ A, const float* __restrict__ W,
               const float* __restrict__ bias, const float* __restrict__ res,
               float* __restrict__ out, int K, int N) {
    extern __shared__ __align__(256) char smem_raw[];
    uint32_t sbase = smem_u32(smem_raw);
    uint32_t* sw = (uint32_t*)smem_raw;

    int tid = threadIdx.x, w = tid >> 5, lane = tid & 31;
    int g = lane >> 2, t = lane & 3;
    int bm = blockIdx.y * 128, bn = blockIdx.x * 128;
    int wm = (w & 1) * 64, wn = (w >> 1) * 64;

    const int nk = K >> 5;

    // 2048 16B-chunks per stage, 16 per thread
    auto load_stage = [&](int s, int k0) {
        uint32_t sb = sbase + s * STAGE_BYTES;
        #pragma unroll
        for (int i = 0; i < 16; i++) {
            int c = tid + 128 * i;
            int row = c >> 3, kq = c & 7;
            const float* src = (row < 128)
                ? (A + (size_t)(bm + row) * K + k0 + kq * 4)
                : (W + (size_t)(bn + row - 128) * K + k0 + kq * 4);
            cpasync16(sb + row * (RSTRIDE * 4) + kq * 16, src);
        }
    };

    float acc[4][8][4];
    #pragma unroll
    for (int mt = 0; mt < 4; mt++)
        #pragma unroll
        for (int nt = 0; nt < 8; nt++)
            #pragma unroll
            for (int q = 0; q < 4; q++) acc[mt][nt][q] = 0.f;

    load_stage(0, 0);
    asm volatile("cp.async.commit_group;" ::: "memory");

    for (int kt = 0; kt < nk; kt++) {
        int s = kt & 1;
        if (kt + 1 < nk) load_stage(s ^ 1, (kt + 1) * 32);
        asm volatile("cp.async.commit_group;" ::: "memory");
        asm volatile("cp.async.wait_group 1;" ::: "memory");   // stage s ready
        __syncthreads();

        const uint32_t* As = sw + (s * STAGE_ROWS) * RSTRIDE;
        const uint32_t* Bs = As + 128 * RSTRIDE;

        #pragma unroll
        for (int kk = 0; kk < 32; kk += 8) {
            uint32_t af[4][4];
            #pragma unroll
            for (int mt = 0; mt < 4; mt++) {
                int r0 = wm + mt * 16 + g;
                uint2 lo = *(const uint2*)&As[r0 * RSTRIDE + kk + 2 * t];
                uint2 hi = *(const uint2*)&As[(r0 + 8) * RSTRIDE + kk + 2 * t];
                af[mt][0] = lo.x; af[mt][2] = lo.y;
                af[mt][1] = hi.x; af[mt][3] = hi.y;
            }
            uint32_t bf[8][2];
            #pragma unroll
            for (int nt = 0; nt < 8; nt++) {
                int c0 = wn + nt * 8 + g;
                uint2 bb = *(const uint2*)&Bs[c0 * RSTRIDE + kk + 2 * t];
                bf[nt][0] = bb.x; bf[nt][1] = bb.y;
            }
            #pragma unroll
            for (int mt = 0; mt < 4; mt++)
                #pragma unroll
                for (int nt = 0; nt < 8; nt++)
                    mma_tf32(acc[mt][nt], af[mt], bf[nt]);
        }
        __syncthreads();   // all reads of stage s done before iter kt+1 refills it
    }

    // epilogue
    #pragma unroll
    for (int mt = 0; mt < 4; mt++) {
        #pragma unroll
        for (int nt = 0; nt < 8; nt++) {
            int rr0 = bm + wm + mt * 16 + g;
            int cc  = bn + wn + nt * 8 + 2 * t;
            float b0 = bias[cc], b1 = bias[cc + 1];
            #pragma unroll
            for (int hh = 0; hh < 2; hh++) {
                int rr = rr0 + hh * 8;
                float v0 = acc[mt][nt][hh * 2 + 0] + b0;
                float v1 = acc[mt][nt][hh * 2 + 1] + b1;
                if (EPI == EPI_RES) {
                    float2 rv = *(const float2*)(res + (size_t)rr * N + cc);
                    v0 += rv.x; v1 += rv.y;
                }
                if (EPI == EPI_GELU) {
                    v0 = rtf(gelu_tanh(v0));
                    v1 = rtf(gelu_tanh(v1));
                }
                *(float2*)(out + (size_t)rr * N + cc) = make_float2(v0, v1);
            }
        }
    }
}

// ---------------- Attention: one block per (b,h), fp32 SIMT -----------------
__global__ __launch_bounds__(128)
void attn_kernel(const float* __restrict__ qkv, const float* __restrict__ abias,
                 const float* __restrict__ bscale_p, float* __restrict__ out) {
    __shared__ float sq[65 * 65];
    __shared__ float skv[65 * 65];

    int bh = blockIdx.x;
    int b  = bh >> 4, h = bh & 15;
    int tid = threadIdx.x;
    size_t base = (size_t)b * SEQ * 3072 + (size_t)h * 64;

    for (int idx = tid; idx < 65 * 64; idx += 128) {
        int n = idx >> 6, d = idx & 63;
        size_t gsrc = base + (size_t)n * 3072 + d;
        sq [n * 65 + d] = qkv[gsrc];
        skv[n * 65 + d] = qkv[gsrc + 1024];
    }
    __syncthreads();

    float bsc = *bscale_p;
    int ty = tid >> 3, tx = tid & 7;

    float acc[5][9];
    #pragma unroll
    for (int i = 0; i < 5; i++)
        #pragma unroll
        for (int j = 0; j < 9; j++) acc[i][j] = 0.f;

    for (int d = 0; d < 64; d++) {
        float qv[5], kv[9];
        #pragma unroll
        for (int i = 0; i < 5; i++) {
            int n = ty + 16 * i; if (n > 64) n = 64;
            qv[i] = sq[n * 65 + d];
        }
        #pragma unroll
        for (int j = 0; j < 9; j++) {
            int m = tx + 8 * j; if (m > 64) m = 64;
            kv[j] = skv[m * 65 + d];
        }
        #pragma unroll
        for (int i = 0; i < 5; i++)
            #pragma unroll
            for (int j = 0; j < 9; j++)
                acc[i][j] += qv[i] * kv[j];
    }

    const float NEG = -1e30f;
    #pragma unroll
    for (int i = 0; i < 5; i++) {
        int n = ty + 16 * i;
        bool valid = (n <= 64);
        int nc = valid ? n : 64;
        const float* brow = abias + ((size_t)h * 65 + nc) * 65;

        float l[9];
        float mx = NEG;
        #pragma unroll
        for (int j = 0; j < 9; j++) {
            int m = tx + 8 * j;
            float lv = NEG;
            if (valid && m <= 64) lv = acc[i][j] * 0.125f + bsc * brow[m];
            l[j] = lv;
            mx = fmaxf(mx, lv);
        }
        mx = fmaxf(mx, __shfl_xor_sync(0xffffffffu, mx, 1));
        mx = fmaxf(mx, __shfl_xor_sync(0xffffffffu, mx, 2));
        mx = fmaxf(mx, __shfl_xor_sync(0xffffffffu, mx, 4));
        float s = 0.f;
        #pragma unroll
        for (int j = 0; j < 9; j++) { l[j] = __expf(l[j] - mx); s += l[j]; }
        s += __shfl_xor_sync(0xffffffffu, s, 1);
        s += __shfl_xor_sync(0xffffffffu, s, 2);
        s += __shfl_xor_sync(0xffffffffu, s, 4);
        float inv = 1.0f / s;
        #pragma unroll
        for (int j = 0; j < 9; j++) {
            int m = tx + 8 * j;
            if (valid && m <= 64) sq[n * 65 + m] = l[j] * inv;
        }
    }
    __syncthreads();

    for (int idx = tid; idx < 65 * 64; idx += 128) {
        int n = idx >> 6, d = idx & 63;
        skv[n * 65 + d] = qkv[base + (size_t)n * 3072 + d + 2048];
    }
    __syncthreads();

    float acc2[5][8];
    #pragma unroll
    for (int i = 0; i < 5; i++)
        #pragma unroll
        for (int j = 0; j < 8; j++) acc2[i][j] = 0.f;

    for (int m = 0; m <= 64; m++) {
        float pv[5], vv[8];
        #pragma unroll
        for (int i = 0; i < 5; i++) {
            int n = ty + 16 * i; if (n > 64) n = 64;
            pv[i] = sq[n * 65 + m];
        }
        #pragma unroll
        for (int j = 0; j < 8; j++)
            vv[j] = skv[m * 65 + tx + 8 * j];
        #pragma unroll
        for (int i = 0; i < 5; i++)
            #pragma unroll
            for (int j = 0; j < 8; j++)
                acc2[i][j] += pv[i] * vv[j];
    }

    size_t obase = (size_t)b * SEQ * 1024 + (size_t)h * 64;
    #pragma unroll
    for (int i = 0; i < 5; i++) {
        int n = ty + 16 * i;
        if (n <= 64) {
            #pragma unroll
            for (int j = 0; j < 8; j++)
                out[obase + (size_t)n * 1024 + tx + 8 * j] = rtf(acc2[i][j]);
        }
    }
}

// ---------------- launch -----------------------------------------------------
extern "C" void kernel_launch(void* const* d_in, const int* in_sizes, int n_in,
                              void* d_out, int out_size) {
    const float* x        = (const float*)d_in[0];
    const float* ln1_g    = (const float*)d_in[1];
    const float* ln1_b    = (const float*)d_in[2];
    const float* qkv_w    = (const float*)d_in[3];
    const float* qkv_b    = (const float*)d_in[4];
    const float* proj_w   = (const float*)d_in[5];
    const float* proj_b   = (const float*)d_in[6];
    const float* attnbias = (const float*)d_in[7];
    const float* bscale   = (const float*)d_in[8];
    const float* ln2_g    = (const float*)d_in[9];
    const float* ln2_b    = (const float*)d_in[10];
    const float* fc1_w    = (const float*)d_in[11];
    const float* fc1_b    = (const float*)d_in[12];
    const float* fc2_w    = (const float*)d_in[13];
    const float* fc2_b    = (const float*)d_in[14];
    float* out = (float*)d_out;

    float *h, *qkv, *att, *act, *wq, *wp, *w1, *w2;
    cudaGetSymbolAddress((void**)&h,   g_h);
    cudaGetSymbolAddress((void**)&qkv, g_qkv);
    cudaGetSymbolAddress((void**)&att, g_att);
    cudaGetSymbolAddress((void**)&act, g_act);
    cudaGetSymbolAddress((void**)&wq,  g_wq);
    cudaGetSymbolAddress((void**)&wp,  g_wp);
    cudaGetSymbolAddress((void**)&w1,  g_w1);
    cudaGetSymbolAddress((void**)&w2,  g_w2);

    cudaFuncSetAttribute(gemm_tf32<EPI_BIAS>, cudaFuncAttributeMaxDynamicSharedMemorySize, GSMEM_TOTAL);
    cudaFuncSetAttribute(gemm_tf32<EPI_RES>,  cudaFuncAttributeMaxDynamicSharedMemorySize, GSMEM_TOTAL);
    cudaFuncSetAttribute(gemm_tf32<EPI_GELU>, cudaFuncAttributeMaxDynamicSharedMemorySize, GSMEM_TOTAL);

    // 0. tf32-round weights into scratch
    round_w<<<512, 256>>>((const float4*)qkv_w,  (float4*)wq, 3 * CC * CC / 4);
    round_w<<<512, 256>>>((const float4*)proj_w, (float4*)wp, CC * CC / 4);
    round_w<<<512, 256>>>((const float4*)fc1_w,  (float4*)w1, HID * CC / 4);
    round_w<<<512, 256>>>((const float4*)fc2_w,  (float4*)w2, CC * HID / 4);

    // 1. h = LN1(x)   (tf32-rounded)
    ln_kernel<<<MTOT, 256>>>(x, ln1_g, ln1_b, h);
    // 2. qkv = h @ qkv_w^T + qkv_b
    gemm_tf32<EPI_BIAS><<<dim3(3 * CC / 128, MTOT / 128), 128, GSMEM_TOTAL>>>(
        h, wq, qkv_b, nullptr, qkv, CC, 3 * CC);
    // 3. attention -> att (tf32-rounded)
    attn_kernel<<<BB * HH, 128>>>(qkv, attnbias, bscale, att);
    // 4. out = x + att @ proj_w^T + proj_b
    gemm_tf32<EPI_RES><<<dim3(CC / 128, MTOT / 128), 128, GSMEM_TOTAL>>>(
        att, wp, proj_b, x, out, CC, CC);
    // 5. h = LN2(out)
    ln_kernel<<<MTOT, 256>>>(out, ln2_g, ln2_b, h);
    // 6. act = gelu(h @ fc1_w^T + fc1_b)  (tf32-rounded)
    gemm_tf32<EPI_GELU><<<dim3(HID / 128, MTOT / 128), 128, GSMEM_TOTAL>>>(
        h, w1, fc1_b, nullptr, act, CC, HID);
    // 7. out = out + act @ fc2_w^T + fc2_b
    gemm_tf32<EPI_RES><<<dim3(CC / 128, MTOT / 128), 128, GSMEM_TOTAL>>>(
        act, w2, fc2_b, out, out, HID, CC);
}

// round 6
// speedup vs baseline: 1.9444x; 1.2727x over previous
#include <cuda_runtime.h>
#include <cuda_fp16.h>
#include <cstdint>
#include <math.h>

#define BB   1024
#define SEQ  65
#define CC   1024
#define HH   16
#define HID  4096
#define MTOT (BB*SEQ)   // 66560 = 520 * 128

// ---------------- scratch (device globals: no allocations allowed) ----------
__device__ __half g_h  [(size_t)MTOT * CC];      // LN output (fp16)
__device__ __half g_qkv[(size_t)MTOT * 3 * CC];  // QKV output (fp16)
__device__ __half g_att[(size_t)MTOT * CC];      // attention output (fp16)
__device__ __half g_act[(size_t)MTOT * HID];     // gelu(fc1) (fp16)
__device__ __half g_wq [(size_t)3 * CC * CC];    // fp16 weights
__device__ __half g_wp [(size_t)CC * CC];
__device__ __half g_w1 [(size_t)HID * CC];
__device__ __half g_w2 [(size_t)CC * HID];

// ---------------- helpers ---------------------------------------------------
__device__ __forceinline__ void mma_f16(float c[4], const uint32_t a[4], const uint32_t b[2]) {
    asm volatile(
        "mma.sync.aligned.m16n8k16.row.col.f32.f16.f16.f32 "
        "{%0,%1,%2,%3}, {%4,%5,%6,%7}, {%8,%9}, {%0,%1,%2,%3};\n"
        : "+f"(c[0]), "+f"(c[1]), "+f"(c[2]), "+f"(c[3])
        : "r"(a[0]), "r"(a[1]), "r"(a[2]), "r"(a[3]), "r"(b[0]), "r"(b[1]));
}

__device__ __forceinline__ void ldsm4(uint32_t r[4], uint32_t addr) {
    asm volatile("ldmatrix.sync.aligned.m8n8.x4.shared.b16 {%0,%1,%2,%3}, [%4];"
        : "=r"(r[0]), "=r"(r[1]), "=r"(r[2]), "=r"(r[3]) : "r"(addr));
}

__device__ __forceinline__ float gelu_tanh(float x) {
    float x3 = x * x * x;
    return 0.5f * x * (1.0f + tanhf(0.7978845608028654f * (x + 0.044715f * x3)));
}

__device__ __forceinline__ uint32_t smem_u32(const void* p) {
    uint32_t a;
    asm("{ .reg .u64 t; cvta.to.shared.u64 t, %1; cvt.u32.u64 %0, t; }" : "=r"(a) : "l"(p));
    return a;
}

__device__ __forceinline__ void cpasync16(uint32_t dst, const void* src) {
    asm volatile("cp.async.cg.shared.global [%0], [%1], 16;" :: "r"(dst), "l"(src));
}

// ---------------- fp32 -> fp16 weight conversion -----------------------------
__global__ __launch_bounds__(256)
void conv_w(const float2* __restrict__ s, __half2* __restrict__ d, int n2) {
    int i = blockIdx.x * blockDim.x + threadIdx.x;
    int stride = gridDim.x * blockDim.x;
    for (; i < n2; i += stride) {
        float2 v = s[i];
        d[i] = __floats2half2_rn(v.x, v.y);
    }
}

// ---------------- LayerNorm (fp16 output) ------------------------------------
__global__ __launch_bounds__(256)
void ln_kernel(const float* __restrict__ x, const float* __restrict__ g,
               const float* __restrict__ b, __half* __restrict__ y) {
    int row = blockIdx.x;
    const float4* xr = (const float4*)(x + (size_t)row * CC);
    float4 v = xr[threadIdx.x];
    float s1 = v.x + v.y + v.z + v.w;
    float s2 = v.x * v.x + v.y * v.y + v.z * v.z + v.w * v.w;
    #pragma unroll
    for (int o = 16; o; o >>= 1) {
        s1 += __shfl_xor_sync(0xffffffffu, s1, o);
        s2 += __shfl_xor_sync(0xffffffffu, s2, o);
    }
    __shared__ float r1[8], r2[8];
    int w = threadIdx.x >> 5;
    if ((threadIdx.x & 31) == 0) { r1[w] = s1; r2[w] = s2; }
    __syncthreads();
    s1 = 0.f; s2 = 0.f;
    #pragma unroll
    for (int i = 0; i < 8; i++) { s1 += r1[i]; s2 += r2[i]; }
    float mu  = s1 * (1.0f / CC);
    float var = s2 * (1.0f / CC) - mu * mu;
    float rs  = rsqrtf(var + 1e-5f);
    float4 gv = ((const float4*)g)[threadIdx.x];
    float4 bv = ((const float4*)b)[threadIdx.x];
    __half2* yr = (__half2*)(y + (size_t)row * CC);
    yr[2 * threadIdx.x + 0] = __floats2half2_rn((v.x - mu) * rs * gv.x + bv.x,
                                                (v.y - mu) * rs * gv.y + bv.y);
    yr[2 * threadIdx.x + 1] = __floats2half2_rn((v.z - mu) * rs * gv.z + bv.z,
                                                (v.w - mu) * rs * gv.w + bv.w);
}

// ---------------- FP16 mma.sync GEMM:  out = A[M,K] @ W[N,K]^T + epi --------
// CTA 128(M) x 128(N) x 64(K-chunk halfs); 4 warps 2x2, warp tile 64x64,
// m16n8k16. 3-stage cp.async ring (32KB/stage) -> 96KB smem, 2 CTAs/SM.
// Rows are 128B (64 halfs); 16B chunk c of row r stored at c ^ (r&7):
// ldmatrix's 8 row-reads hit 8 distinct 16B columns -> conflict-free.
enum { EPI_BIAS = 0, EPI_RES = 1, EPI_GELU = 2 };

#define KCH         64                            // k-chunk in halfs
#define STAGE_BYTES 32768                         // (128+128) rows * 128B
#define NSTAGE      3
#define GSMEM_TOTAL (NSTAGE * STAGE_BYTES)        // 98304

template <int EPI, typename OT>
__global__ __launch_bounds__(128, 2)
void gemm_f16(const __half* __restrict__ A, const __half* __restrict__ W,
              const float* __restrict__ bias, const float* __restrict__ res,
              OT* __restrict__ out, int K, int N) {
    extern __shared__ __align__(256) char smem_raw[];
    uint32_t sbase = smem_u32(smem_raw);

    int tid = threadIdx.x, w = tid >> 5, lane = tid & 31;
    int g = lane >> 2, t = lane & 3;
    int bm = blockIdx.y * 128, bn = blockIdx.x * 128;
    int wm = (w & 1) * 64, wn = (w >> 1) * 64;

    // ldmatrix lane roles
    int j    = lane & 7;
    int bsel = lane >> 3;                 // matrix index 0..3
    int rowA = wm + (bsel & 1) * 8 + j;   // + mt*16
    int cA0  = bsel >> 1;                 // + 2*kb
    int rowB = wn + (bsel >> 1) * 8 + j;  // + p*16
    int cB0  = bsel & 1;                  // + 2*kb

    const int nk = K / KCH;

    // 2048 16B-chunks per stage, 16 per thread
    auto load_stage = [&](int s, int k0) {
        uint32_t sb = sbase + s * STAGE_BYTES;
        #pragma unroll
        for (int i = 0; i < 16; i++) {
            int c = tid + 128 * i;
            int row = c >> 3, ch = c & 7;
            const __half* src = (row < 128)
                ? (A + (size_t)(bm + row) * K + k0 + ch * 8)
                : (W + (size_t)(bn + row - 128) * K + k0 + ch * 8);
            cpasync16(sb + row * 128 + 16 * (ch ^ (row & 7)), src);
        }
        asm volatile("cp.async.commit_group;" ::: "memory");
    };

    float acc[4][8][4];
    #pragma unroll
    for (int mt = 0; mt < 4; mt++)
        #pragma unroll
        for (int nt = 0; nt < 8; nt++)
            #pragma unroll
            for (int q = 0; q < 4; q++) acc[mt][nt][q] = 0.f;

    load_stage(0, 0);
    load_stage(1, KCH);

    for (int kt = 0; kt < nk; kt++) {
        asm volatile("cp.async.wait_group 1;" ::: "memory");  // stage kt ready
        __syncthreads();
        if (kt + 2 < nk) load_stage((kt + 2) % NSTAGE, (kt + 2) * KCH);
        else { asm volatile("cp.async.commit_group;" ::: "memory"); }

        uint32_t Asm = sbase + (kt % NSTAGE) * STAGE_BYTES;
        uint32_t Bsm = Asm + 16384;

        #pragma unroll
        for (int kb = 0; kb < 4; kb++) {
            uint32_t af[4][4];
            #pragma unroll
            for (int mt = 0; mt < 4; mt++) {
                int r = rowA + mt * 16;
                ldsm4(af[mt], Asm + r * 128 + 16 * ((2 * kb + cA0) ^ (r & 7)));
            }
            uint32_t bf[8][2];
            #pragma unroll
            for (int p = 0; p < 4; p++) {
                int n = rowB + p * 16;
                uint32_t tmp[4];
                ldsm4(tmp, Bsm + n * 128 + 16 * ((2 * kb + cB0) ^ (n & 7)));
                bf[2 * p][0]     = tmp[0]; bf[2 * p][1]     = tmp[1];
                bf[2 * p + 1][0] = tmp[2]; bf[2 * p + 1][1] = tmp[3];
            }
            #pragma unroll
            for (int mt = 0; mt < 4; mt++)
                #pragma unroll
                for (int nt = 0; nt < 8; nt++)
                    mma_f16(acc[mt][nt], af[mt], bf[nt]);
        }
        // stage (kt%3) reread-safe: next write to it happens after iter kt+1's
        // top-of-loop barrier, which follows all reads here.
    }

    // epilogue
    #pragma unroll
    for (int mt = 0; mt < 4; mt++) {
        #pragma unroll
        for (int nt = 0; nt < 8; nt++) {
            int rr0 = bm + wm + mt * 16 + g;
            int cc  = bn + wn + nt * 8 + 2 * t;
            float b0 = bias[cc], b1 = bias[cc + 1];
            #pragma unroll
            for (int hh = 0; hh < 2; hh++) {
                int rr = rr0 + hh * 8;
                float v0 = acc[mt][nt][hh * 2 + 0] + b0;
                float v1 = acc[mt][nt][hh * 2 + 1] + b1;
                if (EPI == EPI_RES) {
                    float2 rv = *(const float2*)(res + (size_t)rr * N + cc);
                    v0 += rv.x; v1 += rv.y;
                }
                if (EPI == EPI_GELU) {
                    v0 = gelu_tanh(v0);
                    v1 = gelu_tanh(v1);
                }
                OT* dst = out + (size_t)rr * N + cc;
                if (sizeof(OT) == 2) {
                    *(__half2*)dst = __floats2half2_rn(v0, v1);
                } else {
                    *(float2*)dst = make_float2(v0, v1);
                }
            }
        }
    }
}

// ---------------- Attention: one block per (b,h), fp32 SIMT, fp16 I/O -------
__global__ __launch_bounds__(128)
void attn_kernel(const __half* __restrict__ qkv, const float* __restrict__ abias,
                 const float* __restrict__ bscale_p, __half* __restrict__ out) {
    __shared__ float sq[65 * 65];
    __shared__ float skv[65 * 65];

    int bh = blockIdx.x;
    int b  = bh >> 4, h = bh & 15;
    int tid = threadIdx.x;
    size_t base = (size_t)b * SEQ * 3072 + (size_t)h * 64;

    for (int idx = tid; idx < 65 * 64; idx += 128) {
        int n = idx >> 6, d = idx & 63;
        size_t gsrc = base + (size_t)n * 3072 + d;
        sq [n * 65 + d] = __half2float(qkv[gsrc]);
        skv[n * 65 + d] = __half2float(qkv[gsrc + 1024]);
    }
    __syncthreads();

    float bsc = *bscale_p;
    int ty = tid >> 3, tx = tid & 7;

    float acc[5][9];
    #pragma unroll
    for (int i = 0; i < 5; i++)
        #pragma unroll
        for (int j = 0; j < 9; j++) acc[i][j] = 0.f;

    for (int d = 0; d < 64; d++) {
        float qv[5], kv[9];
        #pragma unroll
        for (int i = 0; i < 5; i++) {
            int n = ty + 16 * i; if (n > 64) n = 64;
            qv[i] = sq[n * 65 + d];
        }
        #pragma unroll
        for (int j = 0; j < 9; j++) {
            int m = tx + 8 * j; if (m > 64) m = 64;
            kv[j] = skv[m * 65 + d];
        }
        #pragma unroll
        for (int i = 0; i < 5; i++)
            #pragma unroll
            for (int j = 0; j < 9; j++)
                acc[i][j] += qv[i] * kv[j];
    }

    const float NEG = -1e30f;
    #pragma unroll
    for (int i = 0; i < 5; i++) {
        int n = ty + 16 * i;
        bool valid = (n <= 64);
        int nc = valid ? n : 64;
        const float* brow = abias + ((size_t)h * 65 + nc) * 65;

        float l[9];
        float mx = NEG;
        #pragma unroll
        for (int j = 0; j < 9; j++) {
            int m = tx + 8 * j;
            float lv = NEG;
            if (valid && m <= 64) lv = acc[i][j] * 0.125f + bsc * brow[m];
            l[j] = lv;
            mx = fmaxf(mx, lv);
        }
        mx = fmaxf(mx, __shfl_xor_sync(0xffffffffu, mx, 1));
        mx = fmaxf(mx, __shfl_xor_sync(0xffffffffu, mx, 2));
        mx = fmaxf(mx, __shfl_xor_sync(0xffffffffu, mx, 4));
        float s = 0.f;
        #pragma unroll
        for (int j = 0; j < 9; j++) { l[j] = __expf(l[j] - mx); s += l[j]; }
        s += __shfl_xor_sync(0xffffffffu, s, 1);
        s += __shfl_xor_sync(0xffffffffu, s, 2);
        s += __shfl_xor_sync(0xffffffffu, s, 4);
        float inv = 1.0f / s;
        #pragma unroll
        for (int j = 0; j < 9; j++) {
            int m = tx + 8 * j;
            if (valid && m <= 64) sq[n * 65 + m] = l[j] * inv;
        }
    }
    __syncthreads();

    for (int idx = tid; idx < 65 * 64; idx += 128) {
        int n = idx >> 6, d = idx & 63;
        skv[n * 65 + d] = __half2float(qkv[base + (size_t)n * 3072 + d + 2048]);
    }
    __syncthreads();

    float acc2[5][8];
    #pragma unroll
    for (int i = 0; i < 5; i++)
        #pragma unroll
        for (int j = 0; j < 8; j++) acc2[i][j] = 0.f;

    for (int m = 0; m <= 64; m++) {
        float pv[5], vv[8];
        #pragma unroll
        for (int i = 0; i < 5; i++) {
            int n = ty + 16 * i; if (n > 64) n = 64;
            pv[i] = sq[n * 65 + m];
        }
        #pragma unroll
        for (int j = 0; j < 8; j++)
            vv[j] = skv[m * 65 + tx + 8 * j];
        #pragma unroll
        for (int i = 0; i < 5; i++)
            #pragma unroll
            for (int j = 0; j < 8; j++)
                acc2[i][j] += pv[i] * vv[j];
    }

    size_t obase = (size_t)b * SEQ * 1024 + (size_t)h * 64;
    #pragma unroll
    for (int i = 0; i < 5; i++) {
        int n = ty + 16 * i;
        if (n <= 64) {
            #pragma unroll
            for (int j = 0; j < 8; j++)
                out[obase + (size_t)n * 1024 + tx + 8 * j] = __float2half_rn(acc2[i][j]);
        }
    }
}

// ---------------- launch -----------------------------------------------------
extern "C" void kernel_launch(void* const* d_in, const int* in_sizes, int n_in,
                              void* d_out, int out_size) {
    const float* x        = (const float*)d_in[0];
    const float* ln1_g    = (const float*)d_in[1];
    const float* ln1_b    = (const float*)d_in[2];
    const float* qkv_w    = (const float*)d_in[3];
    const float* qkv_b    = (const float*)d_in[4];
    const float* proj_w   = (const float*)d_in[5];
    const float* proj_b   = (const float*)d_in[6];
    const float* attnbias = (const float*)d_in[7];
    const float* bscale   = (const float*)d_in[8];
    const float* ln2_g    = (const float*)d_in[9];
    const float* ln2_b    = (const float*)d_in[10];
    const float* fc1_w    = (const float*)d_in[11];
    const float* fc1_b    = (const float*)d_in[12];
    const float* fc2_w    = (const float*)d_in[13];
    const float* fc2_b    = (const float*)d_in[14];
    float* out = (float*)d_out;

    __half *h, *qkv, *att, *act, *wq, *wp, *w1, *w2;
    cudaGetSymbolAddress((void**)&h,   g_h);
    cudaGetSymbolAddress((void**)&qkv, g_qkv);
    cudaGetSymbolAddress((void**)&att, g_att);
    cudaGetSymbolAddress((void**)&act, g_act);
    cudaGetSymbolAddress((void**)&wq,  g_wq);
    cudaGetSymbolAddress((void**)&wp,  g_wp);
    cudaGetSymbolAddress((void**)&w1,  g_w1);
    cudaGetSymbolAddress((void**)&w2,  g_w2);

    cudaFuncSetAttribute((const void*)gemm_f16<EPI_BIAS, __half>,
                         cudaFuncAttributeMaxDynamicSharedMemorySize, GSMEM_TOTAL);
    cudaFuncSetAttribute((const void*)gemm_f16<EPI_RES, float>,
                         cudaFuncAttributeMaxDynamicSharedMemorySize, GSMEM_TOTAL);
    cudaFuncSetAttribute((const void*)gemm_f16<EPI_GELU, __half>,
                         cudaFuncAttributeMaxDynamicSharedMemorySize, GSMEM_TOTAL);

    // 0. fp16 weights
    conv_w<<<512, 256>>>((const float2*)qkv_w,  (__half2*)wq, 3 * CC * CC / 2);
    conv_w<<<512, 256>>>((const float2*)proj_w, (__half2*)wp, CC * CC / 2);
    conv_w<<<512, 256>>>((const float2*)fc1_w,  (__half2*)w1, HID * CC / 2);
    conv_w<<<512, 256>>>((const float2*)fc2_w,  (__half2*)w2, CC * HID / 2);

    // 1. h = LN1(x)   (fp16)
    ln_kernel<<<MTOT, 256>>>(x, ln1_g, ln1_b, h);
    // 2. qkv = h @ qkv_w^T + qkv_b  (fp16 out)
    gemm_f16<EPI_BIAS, __half><<<dim3(3 * CC / 128, MTOT / 128), 128, GSMEM_TOTAL>>>(
        h, wq, qkv_b, nullptr, qkv, CC, 3 * CC);
    // 3. attention -> att (fp16)
    attn_kernel<<<BB * HH, 128>>>(qkv, attnbias, bscale, att);
    // 4. out = x + att @ proj_w^T + proj_b  (fp32 out)
    gemm_f16<EPI_RES, float><<<dim3(CC / 128, MTOT / 128), 128, GSMEM_TOTAL>>>(
        att, wp, proj_b, x, out, CC, CC);
    // 5. h = LN2(out)  (fp16)
    ln_kernel<<<MTOT, 256>>>(out, ln2_g, ln2_b, h);
    // 6. act = gelu(h @ fc1_w^T + fc1_b)  (fp16)
    gemm_f16<EPI_GELU, __half><<<dim3(HID / 128, MTOT / 128), 128, GSMEM_TOTAL>>>(
        h, w1, fc1_b, nullptr, act, CC, HID);
    // 7. out = out + act @ fc2_w^T + fc2_b  (fp32 out)
    gemm_f16<EPI_RES, float><<<dim3(CC / 128, MTOT / 128), 128, GSMEM_TOTAL>>>(
        act, w2, fc2_b, out, out, HID, CC);
}

// round 7
// speedup vs baseline: 3.2571x; 1.6751x over previous
#include <cuda_runtime.h>
#include <cuda_fp16.h>
#include <cstdint>
#include <math.h>

#define BB   1024
#define SEQ  65
#define CC   1024
#define HH   16
#define HID  4096
#define MTOT (BB*SEQ)   // 66560 = 520 * 128

// ---------------- scratch (device globals: no allocations allowed) ----------
__device__ __half g_h  [(size_t)MTOT * CC];      // LN output (fp16)
__device__ __half g_qkv[(size_t)MTOT * 3 * CC];  // QKV output (fp16)
__device__ __half g_att[(size_t)MTOT * CC];      // attention output (fp16)
__device__ __half g_act[(size_t)MTOT * HID];     // gelu(fc1) (fp16)
__device__ __half g_wq [(size_t)3 * CC * CC];    // fp16 weights
__device__ __half g_wp [(size_t)CC * CC];
__device__ __half g_w1 [(size_t)HID * CC];
__device__ __half g_w2 [(size_t)CC * HID];

// ---------------- helpers ---------------------------------------------------
__device__ __forceinline__ void mma_f16(float c[4], const uint32_t a[4], const uint32_t b[2]) {
    asm volatile(
        "mma.sync.aligned.m16n8k16.row.col.f32.f16.f16.f32 "
        "{%0,%1,%2,%3}, {%4,%5,%6,%7}, {%8,%9}, {%0,%1,%2,%3};\n"
        : "+f"(c[0]), "+f"(c[1]), "+f"(c[2]), "+f"(c[3])
        : "r"(a[0]), "r"(a[1]), "r"(a[2]), "r"(a[3]), "r"(b[0]), "r"(b[1]));
}

__device__ __forceinline__ void ldsm4(uint32_t r[4], uint32_t addr) {
    asm volatile("ldmatrix.sync.aligned.m8n8.x4.shared.b16 {%0,%1,%2,%3}, [%4];"
        : "=r"(r[0]), "=r"(r[1]), "=r"(r[2]), "=r"(r[3]) : "r"(addr));
}

__device__ __forceinline__ void ldsm4t(uint32_t r[4], uint32_t addr) {
    asm volatile("ldmatrix.sync.aligned.m8n8.x4.trans.shared.b16 {%0,%1,%2,%3}, [%4];"
        : "=r"(r[0]), "=r"(r[1]), "=r"(r[2]), "=r"(r[3]) : "r"(addr));
}

__device__ __forceinline__ float gelu_tanh(float x) {
    float x3 = x * x * x;
    return 0.5f * x * (1.0f + tanhf(0.7978845608028654f * (x + 0.044715f * x3)));
}

__device__ __forceinline__ uint32_t smem_u32(const void* p) {
    uint32_t a;
    asm("{ .reg .u64 t; cvta.to.shared.u64 t, %1; cvt.u32.u64 %0, t; }" : "=r"(a) : "l"(p));
    return a;
}

__device__ __forceinline__ void cpasync16(uint32_t dst, const void* src) {
    asm volatile("cp.async.cg.shared.global [%0], [%1], 16;" :: "r"(dst), "l"(src));
}

// ---------------- fp32 -> fp16 weight conversion -----------------------------
__global__ __launch_bounds__(256)
void conv_w(const float2* __restrict__ s, __half2* __restrict__ d, int n2) {
    int i = blockIdx.x * blockDim.x + threadIdx.x;
    int stride = gridDim.x * blockDim.x;
    for (; i < n2; i += stride) {
        float2 v = s[i];
        d[i] = __floats2half2_rn(v.x, v.y);
    }
}

// ---------------- LayerNorm (fp16 output) ------------------------------------
__global__ __launch_bounds__(256)
void ln_kernel(const float* __restrict__ x, const float* __restrict__ g,
               const float* __restrict__ b, __half* __restrict__ y) {
    int row = blockIdx.x;
    const float4* xr = (const float4*)(x + (size_t)row * CC);
    float4 v = xr[threadIdx.x];
    float s1 = v.x + v.y + v.z + v.w;
    float s2 = v.x * v.x + v.y * v.y + v.z * v.z + v.w * v.w;
    #pragma unroll
    for (int o = 16; o; o >>= 1) {
        s1 += __shfl_xor_sync(0xffffffffu, s1, o);
        s2 += __shfl_xor_sync(0xffffffffu, s2, o);
    }
    __shared__ float r1[8], r2[8];
    int w = threadIdx.x >> 5;
    if ((threadIdx.x & 31) == 0) { r1[w] = s1; r2[w] = s2; }
    __syncthreads();
    s1 = 0.f; s2 = 0.f;
    #pragma unroll
    for (int i = 0; i < 8; i++) { s1 += r1[i]; s2 += r2[i]; }
    float mu  = s1 * (1.0f / CC);
    float var = s2 * (1.0f / CC) - mu * mu;
    float rs  = rsqrtf(var + 1e-5f);
    float4 gv = ((const float4*)g)[threadIdx.x];
    float4 bv = ((const float4*)b)[threadIdx.x];
    __half2* yr = (__half2*)(y + (size_t)row * CC);
    yr[2 * threadIdx.x + 0] = __floats2half2_rn((v.x - mu) * rs * gv.x + bv.x,
                                                (v.y - mu) * rs * gv.y + bv.y);
    yr[2 * threadIdx.x + 1] = __floats2half2_rn((v.z - mu) * rs * gv.z + bv.z,
                                                (v.w - mu) * rs * gv.w + bv.w);
}

// ---------------- FP16 mma.sync GEMM (unchanged from round 6) ---------------
enum { EPI_BIAS = 0, EPI_RES = 1, EPI_GELU = 2 };

#define KCH         64
#define STAGE_BYTES 32768
#define NSTAGE      3
#define GSMEM_TOTAL (NSTAGE * STAGE_BYTES)

template <int EPI, typename OT>
__global__ __launch_bounds__(128, 2)
void gemm_f16(const __half* __restrict__ A, const __half* __restrict__ W,
              const float* __restrict__ bias, const float* __restrict__ res,
              OT* __restrict__ out, int K, int N) {
    extern __shared__ __align__(256) char smem_raw[];
    uint32_t sbase = smem_u32(smem_raw);

    int tid = threadIdx.x, w = tid >> 5, lane = tid & 31;
    int g = lane >> 2, t = lane & 3;
    int bm = blockIdx.y * 128, bn = blockIdx.x * 128;
    int wm = (w & 1) * 64, wn = (w >> 1) * 64;

    int j    = lane & 7;
    int bsel = lane >> 3;
    int rowA = wm + (bsel & 1) * 8 + j;
    int cA0  = bsel >> 1;
    int rowB = wn + (bsel >> 1) * 8 + j;
    int cB0  = bsel & 1;

    const int nk = K / KCH;

    auto load_stage = [&](int s, int k0) {
        uint32_t sb = sbase + s * STAGE_BYTES;
        #pragma unroll
        for (int i = 0; i < 16; i++) {
            int c = tid + 128 * i;
            int row = c >> 3, ch = c & 7;
            const __half* src = (row < 128)
                ? (A + (size_t)(bm + row) * K + k0 + ch * 8)
                : (W + (size_t)(bn + row - 128) * K + k0 + ch * 8);
            cpasync16(sb + row * 128 + 16 * (ch ^ (row & 7)), src);
        }
        asm volatile("cp.async.commit_group;" ::: "memory");
    };

    float acc[4][8][4];
    #pragma unroll
    for (int mt = 0; mt < 4; mt++)
        #pragma unroll
        for (int nt = 0; nt < 8; nt++)
            #pragma unroll
            for (int q = 0; q < 4; q++) acc[mt][nt][q] = 0.f;

    load_stage(0, 0);
    load_stage(1, KCH);

    for (int kt = 0; kt < nk; kt++) {
        asm volatile("cp.async.wait_group 1;" ::: "memory");
        __syncthreads();
        if (kt + 2 < nk) load_stage((kt + 2) % NSTAGE, (kt + 2) * KCH);
        else { asm volatile("cp.async.commit_group;" ::: "memory"); }

        uint32_t Asm = sbase + (kt % NSTAGE) * STAGE_BYTES;
        uint32_t Bsm = Asm + 16384;

        #pragma unroll
        for (int kb = 0; kb < 4; kb++) {
            uint32_t af[4][4];
            #pragma unroll
            for (int mt = 0; mt < 4; mt++) {
                int r = rowA + mt * 16;
                ldsm4(af[mt], Asm + r * 128 + 16 * ((2 * kb + cA0) ^ (r & 7)));
            }
            uint32_t bf[8][2];
            #pragma unroll
            for (int p = 0; p < 4; p++) {
                int n = rowB + p * 16;
                uint32_t tmp[4];
                ldsm4(tmp, Bsm + n * 128 + 16 * ((2 * kb + cB0) ^ (n & 7)));
                bf[2 * p][0]     = tmp[0]; bf[2 * p][1]     = tmp[1];
                bf[2 * p + 1][0] = tmp[2]; bf[2 * p + 1][1] = tmp[3];
            }
            #pragma unroll
            for (int mt = 0; mt < 4; mt++)
                #pragma unroll
                for (int nt = 0; nt < 8; nt++)
                    mma_f16(acc[mt][nt], af[mt], bf[nt]);
        }
    }

    #pragma unroll
    for (int mt = 0; mt < 4; mt++) {
        #pragma unroll
        for (int nt = 0; nt < 8; nt++) {
            int rr0 = bm + wm + mt * 16 + g;
            int cc  = bn + wn + nt * 8 + 2 * t;
            float b0 = bias[cc], b1 = bias[cc + 1];
            #pragma unroll
            for (int hh = 0; hh < 2; hh++) {
                int rr = rr0 + hh * 8;
                float v0 = acc[mt][nt][hh * 2 + 0] + b0;
                float v1 = acc[mt][nt][hh * 2 + 1] + b1;
                if (EPI == EPI_RES) {
                    float2 rv = *(const float2*)(res + (size_t)rr * N + cc);
                    v0 += rv.x; v1 += rv.y;
                }
                if (EPI == EPI_GELU) {
                    v0 = gelu_tanh(v0);
                    v1 = gelu_tanh(v1);
                }
                OT* dst = out + (size_t)rr * N + cc;
                if (sizeof(OT) == 2) {
                    *(__half2*)dst = __floats2half2_rn(v0, v1);
                } else {
                    *(float2*)dst = make_float2(v0, v1);
                }
            }
        }
    }
}

// ---------------- Attention: fp16 mma flash-style ---------------------------
// One block per (b,h), 160 threads = 5 warps; warp w owns S/O rows [16w,16w+16).
// Seq 65 padded to 80 on both M and N. S = Q@K^T (K is the non-trans B operand),
// softmax in regs (4-lane shfl row reduction, bias + masking), P stored fp16 in
// smem at 176B stride (44 words -> ldmatrix row banks 12j mod 32, conflict-free),
// O = P@V with ldmatrix.x4.trans on XOR-swizzled V.
__global__ __launch_bounds__(160)
void attn_mma(const __half* __restrict__ qkv, const float* __restrict__ abias,
              const float* __restrict__ bscale_p, __half* __restrict__ out) {
    __shared__ __align__(16) __half sQ[80 * 64];
    __shared__ __align__(16) __half sK[80 * 64];
    __shared__ __align__(16) __half sV[80 * 64];
    __shared__ __align__(16) __half sP[80 * 88];

    int bh = blockIdx.x, b = bh >> 4, h = bh & 15;
    int tid = threadIdx.x, w = tid >> 5, lane = tid & 31;
    int g = lane >> 2, t = lane & 3;
    size_t base = (size_t)b * SEQ * 3072 + (size_t)h * 64;

    // load Q,K,V (rows 65..79 zero), XOR-swizzled 128B rows
    for (int idx = tid; idx < 3 * 640; idx += 160) {
        int m = idx / 640, rem = idx - m * 640;
        int row = rem >> 3, ch = rem & 7;
        uint4 v = make_uint4(0, 0, 0, 0);
        if (row < SEQ)
            v = *(const uint4*)(qkv + base + (size_t)row * 3072 + m * 1024 + ch * 8);
        __half* dst = (m == 0) ? sQ : ((m == 1) ? sK : sV);
        *(uint4*)(dst + row * 64 + ((ch ^ (row & 7)) * 8)) = v;
    }
    __syncthreads();

    float bsc = *bscale_p;
    uint32_t sQb = smem_u32(sQ), sKb = smem_u32(sK);
    uint32_t sVb = smem_u32(sV), sPb = smem_u32(sP);

    int j = lane & 7, bsel = lane >> 3;
    int mt = w;  // m-tile 0..4

    // ---- S = Q @ K^T ----
    int rowA = mt * 16 + (bsel & 1) * 8 + j;
    int cA0  = bsel >> 1;
    uint32_t qa[4][4];
    #pragma unroll
    for (int kt = 0; kt < 4; kt++)
        ldsm4(qa[kt], sQb + rowA * 128 + 16 * ((2 * kt + cA0) ^ (rowA & 7)));

    float sacc[10][4];
    #pragma unroll
    for (int nt = 0; nt < 10; nt++)
        #pragma unroll
        for (int q = 0; q < 4; q++) sacc[nt][q] = 0.f;

    int rowKb = (bsel >> 1) * 8 + j;
    int cB0   = bsel & 1;
    #pragma unroll
    for (int nb = 0; nb < 5; nb++) {
        int rK = nb * 16 + rowKb;
        #pragma unroll
        for (int kt = 0; kt < 4; kt++) {
            uint32_t tmp[4];
            ldsm4(tmp, sKb + rK * 128 + 16 * ((2 * kt + cB0) ^ (rK & 7)));
            uint32_t bf0[2] = {tmp[0], tmp[1]}, bf1[2] = {tmp[2], tmp[3]};
            mma_f16(sacc[2 * nb],     qa[kt], bf0);
            mma_f16(sacc[2 * nb + 1], qa[kt], bf1);
        }
    }

    // ---- softmax rows, write P (fp16) ----
    #pragma unroll
    for (int hr = 0; hr < 2; hr++) {
        int r = mt * 16 + g + 8 * hr;
        int rc = (r < SEQ) ? r : (SEQ - 1);
        const float* brow = abias + ((size_t)h * SEQ + rc) * SEQ;
        float l[20];
        float mx = -1e30f;
        #pragma unroll
        for (int nt = 0; nt < 10; nt++) {
            #pragma unroll
            for (int e = 0; e < 2; e++) {
                int c = 8 * nt + 2 * t + e;
                float lv = -1e30f;
                if (r < SEQ && c < SEQ)
                    lv = sacc[nt][2 * hr + e] * 0.125f + bsc * brow[c];
                l[nt * 2 + e] = lv;
                mx = fmaxf(mx, lv);
            }
        }
        mx = fmaxf(mx, __shfl_xor_sync(0xffffffffu, mx, 1));
        mx = fmaxf(mx, __shfl_xor_sync(0xffffffffu, mx, 2));
        float s = 0.f;
        #pragma unroll
        for (int i = 0; i < 20; i++) { l[i] = __expf(l[i] - mx); s += l[i]; }
        s += __shfl_xor_sync(0xffffffffu, s, 1);
        s += __shfl_xor_sync(0xffffffffu, s, 2);
        float inv = 1.0f / s;
        #pragma unroll
        for (int nt = 0; nt < 10; nt++)
            *(__half2*)(sP + r * 88 + 8 * nt + 2 * t) =
                __floats2half2_rn(l[2 * nt] * inv, l[2 * nt + 1] * inv);
    }
    __syncwarp();

    // ---- O = P @ V ----
    float oacc[8][4];
    #pragma unroll
    for (int nt = 0; nt < 8; nt++)
        #pragma unroll
        for (int q = 0; q < 4; q++) oacc[nt][q] = 0.f;

    int rowP = mt * 16 + (bsel & 1) * 8 + j;
    int kl   = lane & 15;
    int ctop = lane >> 4;
    #pragma unroll
    for (int kt = 0; kt < 5; kt++) {
        uint32_t pa[4];
        ldsm4(pa, sPb + rowP * 176 + 16 * (2 * kt + (bsel >> 1)));
        int krow = kt * 16 + kl;
        #pragma unroll
        for (int nb2 = 0; nb2 < 4; nb2++) {
            uint32_t tmp[4];
            int col8 = 2 * nb2 + ctop;
            ldsm4t(tmp, sVb + krow * 128 + 16 * (col8 ^ (krow & 7)));
            uint32_t bf0[2] = {tmp[0], tmp[1]}, bf1[2] = {tmp[2], tmp[3]};
            mma_f16(oacc[2 * nb2],     pa, bf0);
            mma_f16(oacc[2 * nb2 + 1], pa, bf1);
        }
    }

    size_t ob = (size_t)b * SEQ * 1024 + (size_t)h * 64;
    #pragma unroll
    for (int hr = 0; hr < 2; hr++) {
        int r = mt * 16 + g + 8 * hr;
        if (r < SEQ) {
            #pragma unroll
            for (int nt = 0; nt < 8; nt++)
                *(__half2*)(out + ob + (size_t)r * 1024 + 8 * nt + 2 * t) =
                    __floats2half2_rn(oacc[nt][2 * hr], oacc[nt][2 * hr + 1]);
        }
    }
}

// ---------------- launch -----------------------------------------------------
extern "C" void kernel_launch(void* const* d_in, const int* in_sizes, int n_in,
                              void* d_out, int out_size) {
    const float* x        = (const float*)d_in[0];
    const float* ln1_g    = (const float*)d_in[1];
    const float* ln1_b    = (const float*)d_in[2];
    const float* qkv_w    = (const float*)d_in[3];
    const float* qkv_b    = (const float*)d_in[4];
    const float* proj_w   = (const float*)d_in[5];
    const float* proj_b   = (const float*)d_in[6];
    const float* attnbias = (const float*)d_in[7];
    const float* bscale   = (const float*)d_in[8];
    const float* ln2_g    = (const float*)d_in[9];
    const float* ln2_b    = (const float*)d_in[10];
    const float* fc1_w    = (const float*)d_in[11];
    const float* fc1_b    = (const float*)d_in[12];
    const float* fc2_w    = (const float*)d_in[13];
    const float* fc2_b    = (const float*)d_in[14];
    float* out = (float*)d_out;

    __half *h, *qkv, *att, *act, *wq, *wp, *w1, *w2;
    cudaGetSymbolAddress((void**)&h,   g_h);
    cudaGetSymbolAddress((void**)&qkv, g_qkv);
    cudaGetSymbolAddress((void**)&att, g_att);
    cudaGetSymbolAddress((void**)&act, g_act);
    cudaGetSymbolAddress((void**)&wq,  g_wq);
    cudaGetSymbolAddress((void**)&wp,  g_wp);
    cudaGetSymbolAddress((void**)&w1,  g_w1);
    cudaGetSymbolAddress((void**)&w2,  g_w2);

    cudaFuncSetAttribute((const void*)gemm_f16<EPI_BIAS, __half>,
                         cudaFuncAttributeMaxDynamicSharedMemorySize, GSMEM_TOTAL);
    cudaFuncSetAttribute((const void*)gemm_f16<EPI_RES, float>,
                         cudaFuncAttributeMaxDynamicSharedMemorySize, GSMEM_TOTAL);
    cudaFuncSetAttribute((const void*)gemm_f16<EPI_GELU, __half>,
                         cudaFuncAttributeMaxDynamicSharedMemorySize, GSMEM_TOTAL);

    // 0. fp16 weights
    conv_w<<<512, 256>>>((const float2*)qkv_w,  (__half2*)wq, 3 * CC * CC / 2);
    conv_w<<<512, 256>>>((const float2*)proj_w, (__half2*)wp, CC * CC / 2);
    conv_w<<<512, 256>>>((const float2*)fc1_w,  (__half2*)w1, HID * CC / 2);
    conv_w<<<512, 256>>>((const float2*)fc2_w,  (__half2*)w2, CC * HID / 2);

    // 1. h = LN1(x)   (fp16)
    ln_kernel<<<MTOT, 256>>>(x, ln1_g, ln1_b, h);
    // 2. qkv = h @ qkv_w^T + qkv_b  (fp16 out)
    gemm_f16<EPI_BIAS, __half><<<dim3(3 * CC / 128, MTOT / 128), 128, GSMEM_TOTAL>>>(
        h, wq, qkv_b, nullptr, qkv, CC, 3 * CC);
    // 3. attention -> att (fp16), tensor-core path
    attn_mma<<<BB * HH, 160>>>(qkv, attnbias, bscale, att);
    // 4. out = x + att @ proj_w^T + proj_b  (fp32 out)
    gemm_f16<EPI_RES, float><<<dim3(CC / 128, MTOT / 128), 128, GSMEM_TOTAL>>>(
        att, wp, proj_b, x, out, CC, CC);
    // 5. h = LN2(out)  (fp16)
    ln_kernel<<<MTOT, 256>>>(out, ln2_g, ln2_b, h);
    // 6. act = gelu(h @ fc1_w^T + fc1_b)  (fp16)
    gemm_f16<EPI_GELU, __half><<<dim3(HID / 128, MTOT / 128), 128, GSMEM_TOTAL>>>(
        h, w1, fc1_b, nullptr, act, CC, HID);
    // 7. out = out + act @ fc2_w^T + fc2_b  (fp32 out)
    gemm_f16<EPI_RES, float><<<dim3(CC / 128, MTOT / 128), 128, GSMEM_TOTAL>>>(
        act, w2, fc2_b, out, out, HID, CC);
}